// round 1
// baseline (speedup 1.0000x reference)
#include <cuda_runtime.h>
#include <math_constants.h>

// Problem constants
#define BB 4
#define TT 2048
#define EE 1024
#define HH 16
#define DD 64
#define BT (BB*TT)          // 8192

// Scratch (allocation-free rule: __device__ globals)
__device__ float g_q[(size_t)BB*HH*TT*DD];    // [B,H,T,D]
__device__ float g_k[(size_t)BB*HH*TT*DD];
__device__ float g_v[(size_t)BB*HH*TT*DD];
__device__ float g_ctx[(size_t)BB*TT*EE];     // [B,T,H,D] == [B,T,E]

// ---------------------------------------------------------------------------
// Kernel 1: fused QKV projection.
// C[m, n] with m in [0, 8192), n in [0, 3072): n selects (which, h, d).
// q[b,h,t,d] = sum_e x[b,t,e] * Wq[h,e,d]   (same for k, v)
// Tiled 64x64x16, 256 threads, 4x4 microtile per thread.
// ---------------------------------------------------------------------------
__global__ __launch_bounds__(256) void qkv_gemm(
    const float* __restrict__ x,
    const float* __restrict__ Wq, const float* __restrict__ Wk,
    const float* __restrict__ Wv,
    float* __restrict__ qo, float* __restrict__ ko, float* __restrict__ vo)
{
    __shared__ float As[16][65];   // transposed A tile: As[k][m]
    __shared__ float Bs[16][64];   // Bs[k][n]

    const int tx = threadIdx.x, ty = threadIdx.y;
    const int tid = ty * 16 + tx;
    const int n0 = blockIdx.x * 64;     // 0..3071 (head-aligned since 64|n0)
    const int m0 = blockIdx.y * 64;

    const int which = n0 >> 10;                 // 0=q, 1=k, 2=v
    const int h = (n0 & 1023) >> 6;             // head
    const float* W = (which == 0 ? Wq : (which == 1 ? Wk : Wv))
                     + (size_t)h * EE * DD;     // [E][64]

    const int la_m = tid >> 4;   // 0..15
    const int la_k = tid & 15;
    const int lb_e = tid >> 6;   // 0..3
    const int lb_d = tid & 63;

    float c[4][4] = {};

    for (int k0 = 0; k0 < EE; k0 += 16) {
        #pragma unroll
        for (int r = 0; r < 4; ++r) {
            int m = la_m + r * 16;
            As[la_k][m] = x[(size_t)(m0 + m) * EE + k0 + la_k];
        }
        #pragma unroll
        for (int r = 0; r < 4; ++r) {
            int e = lb_e + r * 4;
            Bs[e][lb_d] = W[(size_t)(k0 + e) * DD + lb_d];
        }
        __syncthreads();
        #pragma unroll
        for (int kk = 0; kk < 16; ++kk) {
            float a[4], b[4];
            #pragma unroll
            for (int i = 0; i < 4; ++i) a[i] = As[kk][ty * 4 + i];
            #pragma unroll
            for (int j = 0; j < 4; ++j) b[j] = Bs[kk][tx * 4 + j];
            #pragma unroll
            for (int i = 0; i < 4; ++i)
                #pragma unroll
                for (int j = 0; j < 4; ++j)
                    c[i][j] = fmaf(a[i], b[j], c[i][j]);
        }
        __syncthreads();
    }

    float* outp = (which == 0 ? qo : (which == 1 ? ko : vo));
    #pragma unroll
    for (int i = 0; i < 4; ++i) {
        int m = m0 + ty * 4 + i;
        int b_ = m >> 11;            // /T
        int t_ = m & 2047;
        float* row = outp + (((size_t)b_ * HH + h) * TT + t_) * DD;
        #pragma unroll
        for (int j = 0; j < 4; ++j)
            row[tx * 4 + j] = c[i][j];
    }
}

// ---------------------------------------------------------------------------
// Kernel 2: causal flash attention per (b*h, 64-query tile).
// 64 threads, each owns one query row. q/o in registers, K/V tiles in SMEM
// (broadcast float4 reads, conflict-free), scores staged in padded SMEM.
// ---------------------------------------------------------------------------
__global__ __launch_bounds__(64) void attn_fwd(
    const float* __restrict__ q, const float* __restrict__ k,
    const float* __restrict__ v, const float* __restrict__ amask,
    float* __restrict__ ctx)
{
    const int bh = blockIdx.x;           // 0..63
    const int qt = blockIdx.y;           // 0..31
    const int b_ = bh >> 4;
    const int h  = bh & 15;
    const int tid = threadIdx.x;
    const int t = qt * 64 + tid;

    __shared__ float Ks[64 * 64];
    __shared__ float Vs[64 * 64];
    __shared__ float Ps[64 * 65];        // scores, padded rows

    float qv[64];
    {
        const float4* qp = (const float4*)(q + (((size_t)bh) * TT + t) * DD);
        #pragma unroll
        for (int i = 0; i < 16; ++i) {
            float4 f = qp[i];
            qv[4*i+0] = f.x * 0.125f;   // 1/sqrt(64)
            qv[4*i+1] = f.y * 0.125f;
            qv[4*i+2] = f.z * 0.125f;
            qv[4*i+3] = f.w * 0.125f;
        }
    }
    float o[64];
    #pragma unroll
    for (int d = 0; d < 64; ++d) o[d] = 0.f;
    float m = -CUDART_INF_F, l = 0.f;

    const float* mrow = amask + (size_t)b_ * TT;
    float* prow = &Ps[tid * 65];

    for (int kt = 0; kt <= qt; ++kt) {
        const int s0 = kt * 64;
        {
            const float4* ksrc = (const float4*)(k + (((size_t)bh) * TT + s0) * DD);
            const float4* vsrc = (const float4*)(v + (((size_t)bh) * TT + s0) * DD);
            float4* kd = (float4*)Ks;
            float4* vd = (float4*)Vs;
            for (int i = tid; i < 1024; i += 64) { kd[i] = ksrc[i]; vd[i] = vsrc[i]; }
        }
        __syncthreads();

        const bool diag = (kt == qt);
        float tm = -CUDART_INF_F;
        #pragma unroll 4
        for (int j = 0; j < 64; ++j) {
            const float4* kr = (const float4*)(Ks + j * 64);
            float acc = 0.f;
            #pragma unroll
            for (int dd = 0; dd < 16; ++dd) {
                float4 kf = kr[dd];
                acc = fmaf(qv[4*dd+0], kf.x, acc);
                acc = fmaf(qv[4*dd+1], kf.y, acc);
                acc = fmaf(qv[4*dd+2], kf.z, acc);
                acc = fmaf(qv[4*dd+3], kf.w, acc);
            }
            const int sg = s0 + j;
            acc += (1.0f - mrow[sg]) * -3.4028234663852886e38f;
            if (diag && sg > t) acc = -CUDART_INF_F;
            prow[j] = acc;
            tm = fmaxf(tm, acc);
        }

        const float mn = fmaxf(m, tm);
        const float corr = __expf(m - mn);
        l *= corr;
        #pragma unroll
        for (int d = 0; d < 64; ++d) o[d] *= corr;

        #pragma unroll 4
        for (int j = 0; j < 64; ++j) {
            const float p = __expf(prow[j] - mn);
            l += p;
            const float4* vr = (const float4*)(Vs + j * 64);
            #pragma unroll
            for (int dd = 0; dd < 16; ++dd) {
                float4 vf = vr[dd];
                o[4*dd+0] = fmaf(p, vf.x, o[4*dd+0]);
                o[4*dd+1] = fmaf(p, vf.y, o[4*dd+1]);
                o[4*dd+2] = fmaf(p, vf.z, o[4*dd+2]);
                o[4*dd+3] = fmaf(p, vf.w, o[4*dd+3]);
            }
        }
        m = mn;
        __syncthreads();
    }

    const float inv = 1.0f / l;
    float* op = ctx + (((size_t)(b_ * TT + t)) * HH + h) * DD;
    #pragma unroll
    for (int d = 0; d < 64; ++d) op[d] = o[d] * inv;
}

// ---------------------------------------------------------------------------
// Kernel 3: output projection out = ctx @ Wo^T + bo
// ---------------------------------------------------------------------------
__global__ __launch_bounds__(256) void out_gemm(
    const float* __restrict__ ctx, const float* __restrict__ Wo,
    const float* __restrict__ bo, float* __restrict__ out)
{
    __shared__ float As[16][65];   // As[k][m]
    __shared__ float Bs[16][65];   // Bs[k][n] = Wo[n][k]

    const int tx = threadIdx.x, ty = threadIdx.y;
    const int tid = ty * 16 + tx;
    const int n0 = blockIdx.x * 64;
    const int m0 = blockIdx.y * 64;

    const int la_m = tid >> 4;
    const int la_k = tid & 15;
    const int lb_n = tid >> 4;   // 0..15
    const int lb_e = tid & 15;

    float c[4][4] = {};

    for (int k0 = 0; k0 < EE; k0 += 16) {
        #pragma unroll
        for (int r = 0; r < 4; ++r) {
            int m = la_m + r * 16;
            As[la_k][m] = ctx[(size_t)(m0 + m) * EE + k0 + la_k];
        }
        #pragma unroll
        for (int r = 0; r < 4; ++r) {
            int n = lb_n + r * 16;
            Bs[lb_e][n] = Wo[(size_t)(n0 + n) * EE + k0 + lb_e];
        }
        __syncthreads();
        #pragma unroll
        for (int kk = 0; kk < 16; ++kk) {
            float a[4], b[4];
            #pragma unroll
            for (int i = 0; i < 4; ++i) a[i] = As[kk][ty * 4 + i];
            #pragma unroll
            for (int j = 0; j < 4; ++j) b[j] = Bs[kk][tx * 4 + j];
            #pragma unroll
            for (int i = 0; i < 4; ++i)
                #pragma unroll
                for (int j = 0; j < 4; ++j)
                    c[i][j] = fmaf(a[i], b[j], c[i][j]);
        }
        __syncthreads();
    }

    #pragma unroll
    for (int i = 0; i < 4; ++i) {
        int m = m0 + ty * 4 + i;
        float* row = out + (size_t)m * EE + n0;
        #pragma unroll
        for (int j = 0; j < 4; ++j) {
            int n = tx * 4 + j;
            row[n] = c[i][j] + bo[n0 + n];
        }
    }
}

// ---------------------------------------------------------------------------
// Launch: x, attention_mask, Wq, Wk, Wv, Wo, bo  ->  out [B,T,E] fp32
// ---------------------------------------------------------------------------
extern "C" void kernel_launch(void* const* d_in, const int* in_sizes, int n_in,
                              void* d_out, int out_size)
{
    const float* x     = (const float*)d_in[0];
    const float* amask = (const float*)d_in[1];
    const float* Wq    = (const float*)d_in[2];
    const float* Wk    = (const float*)d_in[3];
    const float* Wv    = (const float*)d_in[4];
    const float* Wo    = (const float*)d_in[5];
    const float* bo    = (const float*)d_in[6];
    float* out = (float*)d_out;

    float *q, *k, *v, *ctx;
    cudaGetSymbolAddress((void**)&q,   g_q);
    cudaGetSymbolAddress((void**)&k,   g_k);
    cudaGetSymbolAddress((void**)&v,   g_v);
    cudaGetSymbolAddress((void**)&ctx, g_ctx);

    {
        dim3 grid(3072 / 64, BT / 64);
        dim3 block(16, 16);
        qkv_gemm<<<grid, block>>>(x, Wq, Wk, Wv, q, k, v);
    }
    {
        dim3 grid(BB * HH, TT / 64);
        attn_fwd<<<grid, 64>>>(q, k, v, amask, ctx);
    }
    {
        dim3 grid(EE / 64, BT / 64);
        dim3 block(16, 16);
        out_gemm<<<grid, block>>>(ctx, Wo, bo, out);
    }
}

// round 3
// speedup vs baseline: 1.5670x; 1.5670x over previous
#include <cuda_runtime.h>
#include <cuda_bf16.h>
#include <math_constants.h>
#include <cstdint>

// Problem constants
#define BB 4
#define TT 2048
#define EE 1024
#define HH 16
#define DD 64
#define BT (BB*TT)          // 8192
#define NQKV 3072

// ---------------------------------------------------------------------------
// Scratch (allocation-free rule: __device__ globals)
// ---------------------------------------------------------------------------
__device__ __align__(16) float g_q[(size_t)BB*HH*TT*DD];    // [B,H,T,D]
__device__ __align__(16) float g_k[(size_t)BB*HH*TT*DD];
__device__ __align__(16) float g_v[(size_t)BB*HH*TT*DD];
__device__ __align__(16) float g_ctx[(size_t)BB*TT*EE];     // [B,T,H*D]

__device__ __align__(16) __nv_bfloat16 g_xhi[(size_t)BT*EE];
__device__ __align__(16) __nv_bfloat16 g_xlo[(size_t)BT*EE];
__device__ __align__(16) __nv_bfloat16 g_wth[(size_t)NQKV*EE];  // W^T for qkv: [n][e]
__device__ __align__(16) __nv_bfloat16 g_wtl[(size_t)NQKV*EE];
__device__ __align__(16) __nv_bfloat16 g_woh[(size_t)EE*EE];    // Wo: [n][e] (K-major)
__device__ __align__(16) __nv_bfloat16 g_wol[(size_t)EE*EE];
__device__ __align__(16) __nv_bfloat16 g_chi[(size_t)BT*EE];
__device__ __align__(16) __nv_bfloat16 g_clo[(size_t)BT*EE];

// ---------------------------------------------------------------------------
// Helpers (base sm_103 ISA only: mma.sync / ldmatrix / cp.async)
// ---------------------------------------------------------------------------
__device__ __forceinline__ uint32_t smem_u32(const void* p) {
    uint32_t a;
    asm("{ .reg .u64 t; cvta.to.shared.u64 t, %1; cvt.u32.u64 %0, t; }"
        : "=r"(a) : "l"(p));
    return a;
}

#define LDSM4(r, addr) \
    asm volatile("ldmatrix.sync.aligned.m8n8.x4.shared.b16 {%0,%1,%2,%3}, [%4];" \
        : "=r"((r)[0]), "=r"((r)[1]), "=r"((r)[2]), "=r"((r)[3]) : "r"(addr))

#define MMA16816(c, a, b0, b1) \
    asm volatile("mma.sync.aligned.m16n8k16.row.col.f32.bf16.bf16.f32 " \
        "{%0,%1,%2,%3}, {%4,%5,%6,%7}, {%8,%9}, {%0,%1,%2,%3};" \
        : "+f"((c)[0]), "+f"((c)[1]), "+f"((c)[2]), "+f"((c)[3]) \
        : "r"((a)[0]), "r"((a)[1]), "r"((a)[2]), "r"((a)[3]), "r"(b0), "r"(b1))

#define CP_ASYNC16(dst, src) \
    asm volatile("cp.async.cg.shared.global [%0], [%1], 16;" :: "r"(dst), "l"(src))
#define CP_COMMIT() asm volatile("cp.async.commit_group;" ::: "memory")

// ---------------------------------------------------------------------------
// Prep: fp32 -> (bf16 hi, bf16 lo) split, elementwise, float4-vectorized
// ---------------------------------------------------------------------------
__global__ __launch_bounds__(256) void conv_hilo(
    const float* __restrict__ s, __nv_bfloat16* __restrict__ hi,
    __nv_bfloat16* __restrict__ lo, int n4)
{
    int i = blockIdx.x * 256 + threadIdx.x;
    if (i >= n4) return;
    float4 v = ((const float4*)s)[i];
    __nv_bfloat162 h0, h1, l0, l1;
    h0.x = __float2bfloat16(v.x); h0.y = __float2bfloat16(v.y);
    h1.x = __float2bfloat16(v.z); h1.y = __float2bfloat16(v.w);
    l0.x = __float2bfloat16(v.x - __bfloat162float(h0.x));
    l0.y = __float2bfloat16(v.y - __bfloat162float(h0.y));
    l1.x = __float2bfloat16(v.z - __bfloat162float(h1.x));
    l1.y = __float2bfloat16(v.w - __bfloat162float(h1.y));
    ((__nv_bfloat162*)hi)[i * 2 + 0] = h0;
    ((__nv_bfloat162*)hi)[i * 2 + 1] = h1;
    ((__nv_bfloat162*)lo)[i * 2 + 0] = l0;
    ((__nv_bfloat162*)lo)[i * 2 + 1] = l1;
}

// ---------------------------------------------------------------------------
// Prep: transpose+split qkv weights. W[h][e][d] -> Wt[n][e], n = which*1024+h*64+d
// ---------------------------------------------------------------------------
__global__ __launch_bounds__(256) void prep_wt(
    const float* __restrict__ Wq, const float* __restrict__ Wk,
    const float* __restrict__ Wv,
    __nv_bfloat16* __restrict__ th, __nv_bfloat16* __restrict__ tl)
{
    __shared__ float ts[64][65];
    const int bx = blockIdx.x;
    const int mi = bx >> 8;
    const int rem = bx & 255;
    const int h = rem >> 4;
    const int e0 = (rem & 15) * 64;
    const float* src = (mi == 0 ? Wq : (mi == 1 ? Wk : Wv)) + (size_t)h * EE * DD;
    const int tid = threadIdx.x;

    #pragma unroll
    for (int i = 0; i < 4; ++i) {
        int idx = tid + i * 256;
        int ei = idx >> 4, d4 = idx & 15;
        float4 v = ((const float4*)(src + (size_t)(e0 + ei) * DD))[d4];
        ts[ei][d4 * 4 + 0] = v.x; ts[ei][d4 * 4 + 1] = v.y;
        ts[ei][d4 * 4 + 2] = v.z; ts[ei][d4 * 4 + 3] = v.w;
    }
    __syncthreads();

    const int d = tid >> 2, seg = tid & 3;
    const size_t row = ((size_t)mi * 1024 + h * 64 + d) * EE + e0 + seg * 16;
    alignas(16) __nv_bfloat16 hb[16], lb[16];
    #pragma unroll
    for (int i = 0; i < 16; ++i) {
        float v = ts[seg * 16 + i][d];
        __nv_bfloat16 hv = __float2bfloat16(v);
        hb[i] = hv;
        lb[i] = __float2bfloat16(v - __bfloat162float(hv));
    }
    *(uint4*)(th + row)     = *(const uint4*)(hb);
    *(uint4*)(th + row + 8) = *(const uint4*)(hb + 8);
    *(uint4*)(tl + row)     = *(const uint4*)(lb);
    *(uint4*)(tl + row + 8) = *(const uint4*)(lb + 8);
}

// ---------------------------------------------------------------------------
// HMMA split-bf16 GEMM: C[m0+128, n0+128] = sum_k A[m][k]*B[n][k]
//   fp32 ~= hi+lo;  C = Ahi*Bhi + Ahi*Blo + Alo*Bhi  (fp32 accumulate)
// Block 128x128x32, 8 warps (4M x 2N), warp tile 32x64.
// SMEM: pitch-40 bf16 rows (conflict-free ldmatrix), cp.async double-buffered.
// mode 0: scatter to q/k/v [B,H,T,D].  mode 1: out = C + bias, row-major.
// ---------------------------------------------------------------------------
#define PITCH 40
#define SPLIT_ELEMS (128 * PITCH)       // 5120 elems per (array) per stage
#define STAGE_BYTES (4 * SPLIT_ELEMS * 2)  // 40960

__global__ __launch_bounds__(256, 1)
void mma_gemm(const __nv_bfloat16* __restrict__ Ah, const __nv_bfloat16* __restrict__ Al,
              const __nv_bfloat16* __restrict__ Bh, const __nv_bfloat16* __restrict__ Bl,
              const float* __restrict__ bias,
              float* __restrict__ oq, float* __restrict__ okk, float* __restrict__ ov,
              float* __restrict__ oplain, int mode)
{
    extern __shared__ char sm[];
    const uint32_t sbase = smem_u32(sm);
    const int tid = threadIdx.x;
    const int wid = tid >> 5, lane = tid & 31;
    const int wm = wid & 3, wn = wid >> 2;      // 4 M-warps x 2 N-warps
    const int n0 = blockIdx.x * 128;
    const int m0 = blockIdx.y * 128;

    // ldmatrix lane offsets
    const int a_row = lane & 15;
    const int a_col = (lane >> 4) << 3;
    const int b_row = ((lane >> 4) << 3) + (lane & 7);
    const int b_col = ((lane >> 3) & 1) << 3;

    float c[2][8][4] = {};

    // --- stage loader (cp.async, 16B granules) ---
    auto stage_load = [&](int buf, int k0) {
        #pragma unroll
        for (int t = 0; t < 8; ++t) {
            const int arr = t >> 1;                       // 0:Ah 1:Al 2:Bh 3:Bl
            const int local = ((t & 1) << 8) + tid;       // 0..511
            const int r = local >> 2, seg = local & 3;
            const __nv_bfloat16* gb =
                (arr == 0) ? Ah : (arr == 1) ? Al : (arr == 2) ? Bh : Bl;
            const int row0 = (arr < 2) ? m0 : n0;
            const __nv_bfloat16* g = gb + (size_t)(row0 + r) * EE + k0 + seg * 8;
            uint32_t dst = sbase + buf * STAGE_BYTES
                         + (uint32_t)(arr * SPLIT_ELEMS + r * PITCH + seg * 8) * 2;
            CP_ASYNC16(dst, g);
        }
        CP_COMMIT();
    };

    stage_load(0, 0);
    stage_load(1, 32);

    for (int ch = 0; ch < 32; ++ch) {
        if (ch < 31) asm volatile("cp.async.wait_group 1;" ::: "memory");
        else         asm volatile("cp.async.wait_group 0;" ::: "memory");
        __syncthreads();

        const uint32_t sAh = sbase + (ch & 1) * STAGE_BYTES;
        const uint32_t sAl = sAh + SPLIT_ELEMS * 2;
        const uint32_t sBh = sAh + 2 * SPLIT_ELEMS * 2;
        const uint32_t sBl = sAh + 3 * SPLIT_ELEMS * 2;

        #pragma unroll
        for (int ks = 0; ks < 2; ++ks) {
            uint32_t ah[2][4], alr[2][4], bh[4][4], bl[4][4];
            #pragma unroll
            for (int mi = 0; mi < 2; ++mi) {
                uint32_t off = (uint32_t)((wm * 32 + mi * 16 + a_row) * PITCH
                                          + ks * 16 + a_col) * 2;
                LDSM4(ah[mi],  sAh + off);
                LDSM4(alr[mi], sAl + off);
            }
            #pragma unroll
            for (int jp = 0; jp < 4; ++jp) {
                uint32_t off = (uint32_t)((wn * 64 + jp * 16 + b_row) * PITCH
                                          + ks * 16 + b_col) * 2;
                LDSM4(bh[jp], sBh + off);
                LDSM4(bl[jp], sBl + off);
            }
            #pragma unroll
            for (int mi = 0; mi < 2; ++mi)
                #pragma unroll
                for (int nt = 0; nt < 8; ++nt) {
                    const int jp = nt >> 1, q = (nt & 1) * 2;
                    MMA16816(c[mi][nt], ah[mi],  bh[jp][q], bh[jp][q + 1]);
                    MMA16816(c[mi][nt], ah[mi],  bl[jp][q], bl[jp][q + 1]);
                    MMA16816(c[mi][nt], alr[mi], bh[jp][q], bh[jp][q + 1]);
                }
        }
        __syncthreads();
        if (ch + 2 < 32) stage_load(ch & 1, (ch + 2) * 32);
    }

    // --- epilogue: direct float2 stores from C-fragment layout ---
    const int rbase = m0 + wm * 32 + (lane >> 2);
    const int cpair = (lane & 3) * 2;

    if (mode == 0) {
        const int which = n0 >> 10;
        float* outp = (which == 0) ? oq : (which == 1) ? okk : ov;
        const int h = ((n0 & 1023) >> 6) + wn;
        #pragma unroll
        for (int mi = 0; mi < 2; ++mi) {
            const int m1 = rbase + mi * 16;
            const int b1 = m1 >> 11, t1 = m1 & 2047;
            float* base1 = outp + (((size_t)b1 * HH + h) * TT + t1) * DD;
            float* base2 = outp + (((size_t)((m1+8) >> 11)) * HH + h) * TT * DD
                         + (size_t)((m1 + 8) & 2047) * DD;
            #pragma unroll
            for (int nt = 0; nt < 8; ++nt) {
                const int d = nt * 8 + cpair;
                float2 v1 = make_float2(c[mi][nt][0], c[mi][nt][1]);
                float2 v2 = make_float2(c[mi][nt][2], c[mi][nt][3]);
                *(float2*)(base1 + d) = v1;
                *(float2*)(base2 + d) = v2;
            }
        }
    } else {
        #pragma unroll
        for (int mi = 0; mi < 2; ++mi) {
            const int m1 = rbase + mi * 16;
            float* r1 = oplain + (size_t)m1 * EE;
            float* r2 = oplain + (size_t)(m1 + 8) * EE;
            #pragma unroll
            for (int nt = 0; nt < 8; ++nt) {
                const int col = n0 + wn * 64 + nt * 8 + cpair;
                const float b0 = bias[col], b1v = bias[col + 1];
                float2 v1 = make_float2(c[mi][nt][0] + b0, c[mi][nt][1] + b1v);
                float2 v2 = make_float2(c[mi][nt][2] + b0, c[mi][nt][3] + b1v);
                *(float2*)(r1 + col) = v1;
                *(float2*)(r2 + col) = v2;
            }
        }
    }
}

// ---------------------------------------------------------------------------
// Kernel 2: causal flash attention (unchanged, known-correct)
// ---------------------------------------------------------------------------
__global__ __launch_bounds__(64) void attn_fwd(
    const float* __restrict__ q, const float* __restrict__ k,
    const float* __restrict__ v, const float* __restrict__ amask,
    float* __restrict__ ctx)
{
    const int bh = blockIdx.x;
    const int qt = blockIdx.y;
    const int b_ = bh >> 4;
    const int h  = bh & 15;
    const int tid = threadIdx.x;
    const int t = qt * 64 + tid;

    __shared__ float Ks[64 * 64];
    __shared__ float Vs[64 * 64];
    __shared__ float Ps[64 * 65];

    float qv[64];
    {
        const float4* qp = (const float4*)(q + (((size_t)bh) * TT + t) * DD);
        #pragma unroll
        for (int i = 0; i < 16; ++i) {
            float4 f = qp[i];
            qv[4*i+0] = f.x * 0.125f;
            qv[4*i+1] = f.y * 0.125f;
            qv[4*i+2] = f.z * 0.125f;
            qv[4*i+3] = f.w * 0.125f;
        }
    }
    float o[64];
    #pragma unroll
    for (int d = 0; d < 64; ++d) o[d] = 0.f;
    float m = -CUDART_INF_F, l = 0.f;

    const float* mrow = amask + (size_t)b_ * TT;
    float* prow = &Ps[tid * 65];

    for (int kt = 0; kt <= qt; ++kt) {
        const int s0 = kt * 64;
        {
            const float4* ksrc = (const float4*)(k + (((size_t)bh) * TT + s0) * DD);
            const float4* vsrc = (const float4*)(v + (((size_t)bh) * TT + s0) * DD);
            float4* kd = (float4*)Ks;
            float4* vd = (float4*)Vs;
            for (int i = tid; i < 1024; i += 64) { kd[i] = ksrc[i]; vd[i] = vsrc[i]; }
        }
        __syncthreads();

        const bool diag = (kt == qt);
        float tm = -CUDART_INF_F;
        #pragma unroll 4
        for (int j = 0; j < 64; ++j) {
            const float4* kr = (const float4*)(Ks + j * 64);
            float acc = 0.f;
            #pragma unroll
            for (int dd = 0; dd < 16; ++dd) {
                float4 kf = kr[dd];
                acc = fmaf(qv[4*dd+0], kf.x, acc);
                acc = fmaf(qv[4*dd+1], kf.y, acc);
                acc = fmaf(qv[4*dd+2], kf.z, acc);
                acc = fmaf(qv[4*dd+3], kf.w, acc);
            }
            const int sg = s0 + j;
            acc += (1.0f - mrow[sg]) * -3.4028234663852886e38f;
            if (diag && sg > t) acc = -CUDART_INF_F;
            prow[j] = acc;
            tm = fmaxf(tm, acc);
        }

        const float mn = fmaxf(m, tm);
        const float corr = __expf(m - mn);
        l *= corr;
        #pragma unroll
        for (int d = 0; d < 64; ++d) o[d] *= corr;

        #pragma unroll 4
        for (int j = 0; j < 64; ++j) {
            const float p = __expf(prow[j] - mn);
            l += p;
            const float4* vr = (const float4*)(Vs + j * 64);
            #pragma unroll
            for (int dd = 0; dd < 16; ++dd) {
                float4 vf = vr[dd];
                o[4*dd+0] = fmaf(p, vf.x, o[4*dd+0]);
                o[4*dd+1] = fmaf(p, vf.y, o[4*dd+1]);
                o[4*dd+2] = fmaf(p, vf.z, o[4*dd+2]);
                o[4*dd+3] = fmaf(p, vf.w, o[4*dd+3]);
            }
        }
        m = mn;
        __syncthreads();
    }

    const float inv = 1.0f / l;
    float* op = ctx + (((size_t)(b_ * TT + t)) * HH + h) * DD;
    #pragma unroll
    for (int d = 0; d < 64; ++d) op[d] = o[d] * inv;
}

// ---------------------------------------------------------------------------
// Launch
// ---------------------------------------------------------------------------
extern "C" void kernel_launch(void* const* d_in, const int* in_sizes, int n_in,
                              void* d_out, int out_size)
{
    const float* x     = (const float*)d_in[0];
    const float* amask = (const float*)d_in[1];
    const float* Wq    = (const float*)d_in[2];
    const float* Wk    = (const float*)d_in[3];
    const float* Wv    = (const float*)d_in[4];
    const float* Wo    = (const float*)d_in[5];
    const float* bo    = (const float*)d_in[6];
    float* out = (float*)d_out;

    float *q, *k, *v, *ctx;
    __nv_bfloat16 *xhi, *xlo, *wth, *wtl, *woh, *wol, *chi, *clo;
    cudaGetSymbolAddress((void**)&q,   g_q);
    cudaGetSymbolAddress((void**)&k,   g_k);
    cudaGetSymbolAddress((void**)&v,   g_v);
    cudaGetSymbolAddress((void**)&ctx, g_ctx);
    cudaGetSymbolAddress((void**)&xhi, g_xhi);
    cudaGetSymbolAddress((void**)&xlo, g_xlo);
    cudaGetSymbolAddress((void**)&wth, g_wth);
    cudaGetSymbolAddress((void**)&wtl, g_wtl);
    cudaGetSymbolAddress((void**)&woh, g_woh);
    cudaGetSymbolAddress((void**)&wol, g_wol);
    cudaGetSymbolAddress((void**)&chi, g_chi);
    cudaGetSymbolAddress((void**)&clo, g_clo);

    cudaFuncSetAttribute(mma_gemm, cudaFuncAttributeMaxDynamicSharedMemorySize,
                         2 * STAGE_BYTES);

    conv_hilo<<<(BT * EE / 4) / 256, 256>>>(x, xhi, xlo, BT * EE / 4);
    prep_wt<<<768, 256>>>(Wq, Wk, Wv, wth, wtl);
    conv_hilo<<<(EE * EE / 4) / 256, 256>>>(Wo, woh, wol, EE * EE / 4);

    {
        dim3 grid(NQKV / 128, BT / 128);
        mma_gemm<<<grid, 256, 2 * STAGE_BYTES>>>(xhi, xlo, wth, wtl, nullptr,
                                                 q, k, v, nullptr, 0);
    }
    {
        dim3 grid(BB * HH, TT / 64);
        attn_fwd<<<grid, 64>>>(q, k, v, amask, ctx);
    }
    conv_hilo<<<(BT * EE / 4) / 256, 256>>>(ctx, chi, clo, BT * EE / 4);
    {
        dim3 grid(EE / 128, BT / 128);
        mma_gemm<<<grid, 256, 2 * STAGE_BYTES>>>(chi, clo, woh, wol, bo,
                                                 nullptr, nullptr, nullptr, out, 1);
    }
}

// round 4
// speedup vs baseline: 3.1824x; 2.0309x over previous
#include <cuda_runtime.h>
#include <cuda_bf16.h>
#include <math_constants.h>
#include <cstdint>

// Problem constants
#define BB 4
#define TT 2048
#define EE 1024
#define HH 16
#define DD 64
#define BT (BB*TT)          // 8192
#define NQKV 3072

#define L2E 1.44269504f
#define SCALE_Q (0.125f * L2E)    // fold 1/sqrt(D) and log2(e) into q

// ---------------------------------------------------------------------------
// Scratch (allocation-free rule: __device__ globals)
// ---------------------------------------------------------------------------
__device__ __align__(16) float g_ctx[(size_t)BB*TT*EE];     // [B,T,H*D]

__device__ __align__(16) __nv_bfloat16 g_xhi[(size_t)BT*EE];
__device__ __align__(16) __nv_bfloat16 g_xlo[(size_t)BT*EE];
__device__ __align__(16) __nv_bfloat16 g_wth[(size_t)NQKV*EE];
__device__ __align__(16) __nv_bfloat16 g_wtl[(size_t)NQKV*EE];
__device__ __align__(16) __nv_bfloat16 g_woh[(size_t)EE*EE];
__device__ __align__(16) __nv_bfloat16 g_wol[(size_t)EE*EE];
__device__ __align__(16) __nv_bfloat16 g_chi[(size_t)BT*EE];
__device__ __align__(16) __nv_bfloat16 g_clo[(size_t)BT*EE];

// bf16 hi/lo q,k,v in [B,H,T,D]
__device__ __align__(16) __nv_bfloat16 g_qh[(size_t)BB*HH*TT*DD];
__device__ __align__(16) __nv_bfloat16 g_ql[(size_t)BB*HH*TT*DD];
__device__ __align__(16) __nv_bfloat16 g_kh[(size_t)BB*HH*TT*DD];
__device__ __align__(16) __nv_bfloat16 g_kl[(size_t)BB*HH*TT*DD];
__device__ __align__(16) __nv_bfloat16 g_vh[(size_t)BB*HH*TT*DD];
__device__ __align__(16) __nv_bfloat16 g_vl[(size_t)BB*HH*TT*DD];

// ---------------------------------------------------------------------------
// Helpers (base sm_103 ISA: mma.sync / ldmatrix / cp.async)
// ---------------------------------------------------------------------------
__device__ __forceinline__ uint32_t smem_u32(const void* p) {
    uint32_t a;
    asm("{ .reg .u64 t; cvta.to.shared.u64 t, %1; cvt.u32.u64 %0, t; }"
        : "=r"(a) : "l"(p));
    return a;
}

#define LDSM4(r, addr) \
    asm volatile("ldmatrix.sync.aligned.m8n8.x4.shared.b16 {%0,%1,%2,%3}, [%4];" \
        : "=r"((r)[0]), "=r"((r)[1]), "=r"((r)[2]), "=r"((r)[3]) : "r"(addr))

#define LDSM4T(r, addr) \
    asm volatile("ldmatrix.sync.aligned.m8n8.x4.trans.shared.b16 {%0,%1,%2,%3}, [%4];" \
        : "=r"((r)[0]), "=r"((r)[1]), "=r"((r)[2]), "=r"((r)[3]) : "r"(addr))

#define MMA16816(c, a, b0, b1) \
    asm volatile("mma.sync.aligned.m16n8k16.row.col.f32.bf16.bf16.f32 " \
        "{%0,%1,%2,%3}, {%4,%5,%6,%7}, {%8,%9}, {%0,%1,%2,%3};" \
        : "+f"((c)[0]), "+f"((c)[1]), "+f"((c)[2]), "+f"((c)[3]) \
        : "r"((a)[0]), "r"((a)[1]), "r"((a)[2]), "r"((a)[3]), "r"(b0), "r"(b1))

#define CP_ASYNC16(dst, src) \
    asm volatile("cp.async.cg.shared.global [%0], [%1], 16;" :: "r"(dst), "l"(src))
#define CP_COMMIT() asm volatile("cp.async.commit_group;" ::: "memory")

// split two floats into packed bf16x2 hi and lo residual
__device__ __forceinline__ void split2(float a, float b, uint32_t& hi, uint32_t& lo) {
    __nv_bfloat16 ha = __float2bfloat16(a), hb = __float2bfloat16(b);
    float ra = a - __bfloat162float(ha);
    float rb = b - __bfloat162float(hb);
    __nv_bfloat162 H; H.x = ha; H.y = hb;
    __nv_bfloat162 L; L.x = __float2bfloat16(ra); L.y = __float2bfloat16(rb);
    hi = *(uint32_t*)&H;
    lo = *(uint32_t*)&L;
}

// fast exp2 on the FMA pipe (degree-7 Taylor, rel err ~1e-6), x arbitrary <= ~0
__device__ __forceinline__ float exp2fast(float x) {
    x = fmaxf(x, -125.0f);
    int n = __float2int_rd(x);
    float f = x - (float)n;
    float p = 1.3570247e-5f;
    p = fmaf(p, f, 1.5353362e-4f);
    p = fmaf(p, f, 1.3398874e-3f);
    p = fmaf(p, f, 9.6184374e-3f);
    p = fmaf(p, f, 5.5503325e-2f);
    p = fmaf(p, f, 2.4022648e-1f);
    p = fmaf(p, f, 6.9314720e-1f);
    p = fmaf(p, f, 1.0f);
    return p * __int_as_float((n + 127) << 23);
}

// ---------------------------------------------------------------------------
// Prep: fp32 -> (bf16 hi, bf16 lo)
// ---------------------------------------------------------------------------
__global__ __launch_bounds__(256) void conv_hilo(
    const float* __restrict__ s, __nv_bfloat16* __restrict__ hi,
    __nv_bfloat16* __restrict__ lo, int n4)
{
    int i = blockIdx.x * 256 + threadIdx.x;
    if (i >= n4) return;
    float4 v = ((const float4*)s)[i];
    uint32_t h0, l0, h1, l1;
    split2(v.x, v.y, h0, l0);
    split2(v.z, v.w, h1, l1);
    ((uint32_t*)hi)[i * 2 + 0] = h0;
    ((uint32_t*)hi)[i * 2 + 1] = h1;
    ((uint32_t*)lo)[i * 2 + 0] = l0;
    ((uint32_t*)lo)[i * 2 + 1] = l1;
}

// ---------------------------------------------------------------------------
// Prep: transpose+split qkv weights. W[h][e][d] -> Wt[n][e]
// ---------------------------------------------------------------------------
__global__ __launch_bounds__(256) void prep_wt(
    const float* __restrict__ Wq, const float* __restrict__ Wk,
    const float* __restrict__ Wv,
    __nv_bfloat16* __restrict__ th, __nv_bfloat16* __restrict__ tl)
{
    __shared__ float ts[64][65];
    const int bx = blockIdx.x;
    const int mi = bx >> 8;
    const int rem = bx & 255;
    const int h = rem >> 4;
    const int e0 = (rem & 15) * 64;
    const float* src = (mi == 0 ? Wq : (mi == 1 ? Wk : Wv)) + (size_t)h * EE * DD;
    const int tid = threadIdx.x;

    #pragma unroll
    for (int i = 0; i < 4; ++i) {
        int idx = tid + i * 256;
        int ei = idx >> 4, d4 = idx & 15;
        float4 v = ((const float4*)(src + (size_t)(e0 + ei) * DD))[d4];
        ts[ei][d4 * 4 + 0] = v.x; ts[ei][d4 * 4 + 1] = v.y;
        ts[ei][d4 * 4 + 2] = v.z; ts[ei][d4 * 4 + 3] = v.w;
    }
    __syncthreads();

    const int d = tid >> 2, seg = tid & 3;
    const size_t row = ((size_t)mi * 1024 + h * 64 + d) * EE + e0 + seg * 16;
    alignas(16) __nv_bfloat16 hb[16], lb[16];
    #pragma unroll
    for (int i = 0; i < 16; ++i) {
        float v = ts[seg * 16 + i][d];
        __nv_bfloat16 hv = __float2bfloat16(v);
        hb[i] = hv;
        lb[i] = __float2bfloat16(v - __bfloat162float(hv));
    }
    *(uint4*)(th + row)     = *(const uint4*)(hb);
    *(uint4*)(th + row + 8) = *(const uint4*)(hb + 8);
    *(uint4*)(tl + row)     = *(const uint4*)(lb);
    *(uint4*)(tl + row + 8) = *(const uint4*)(lb + 8);
}

// ---------------------------------------------------------------------------
// HMMA split-bf16 GEMM (proven R3). mode 0: epilogue emits bf16 hi/lo q/k/v
// (with SCALE_Q folded into q). mode 1: fp32 out = C + bias.
// ---------------------------------------------------------------------------
#define PITCH 40
#define SPLIT_ELEMS (128 * PITCH)
#define STAGE_BYTES (4 * SPLIT_ELEMS * 2)

__global__ __launch_bounds__(256, 1)
void mma_gemm(const __nv_bfloat16* __restrict__ Ah, const __nv_bfloat16* __restrict__ Al,
              const __nv_bfloat16* __restrict__ Bh, const __nv_bfloat16* __restrict__ Bl,
              const float* __restrict__ bias,
              __nv_bfloat16* __restrict__ qh, __nv_bfloat16* __restrict__ ql,
              __nv_bfloat16* __restrict__ kh, __nv_bfloat16* __restrict__ kl,
              __nv_bfloat16* __restrict__ vh, __nv_bfloat16* __restrict__ vl,
              float* __restrict__ oplain, int mode)
{
    extern __shared__ char sm[];
    const uint32_t sbase = smem_u32(sm);
    const int tid = threadIdx.x;
    const int wid = tid >> 5, lane = tid & 31;
    const int wm = wid & 3, wn = wid >> 2;
    const int n0 = blockIdx.x * 128;
    const int m0 = blockIdx.y * 128;

    const int a_row = lane & 15;
    const int a_col = (lane >> 4) << 3;
    const int b_row = ((lane >> 4) << 3) + (lane & 7);
    const int b_col = ((lane >> 3) & 1) << 3;

    float c[2][8][4] = {};

    auto stage_load = [&](int buf, int k0) {
        #pragma unroll
        for (int t = 0; t < 8; ++t) {
            const int arr = t >> 1;
            const int local = ((t & 1) << 8) + tid;
            const int r = local >> 2, seg = local & 3;
            const __nv_bfloat16* gb =
                (arr == 0) ? Ah : (arr == 1) ? Al : (arr == 2) ? Bh : Bl;
            const int row0 = (arr < 2) ? m0 : n0;
            const __nv_bfloat16* g = gb + (size_t)(row0 + r) * EE + k0 + seg * 8;
            uint32_t dst = sbase + buf * STAGE_BYTES
                         + (uint32_t)(arr * SPLIT_ELEMS + r * PITCH + seg * 8) * 2;
            CP_ASYNC16(dst, g);
        }
        CP_COMMIT();
    };

    stage_load(0, 0);
    stage_load(1, 32);

    for (int ch = 0; ch < 32; ++ch) {
        if (ch < 31) asm volatile("cp.async.wait_group 1;" ::: "memory");
        else         asm volatile("cp.async.wait_group 0;" ::: "memory");
        __syncthreads();

        const uint32_t sAh = sbase + (ch & 1) * STAGE_BYTES;
        const uint32_t sAl = sAh + SPLIT_ELEMS * 2;
        const uint32_t sBh = sAh + 2 * SPLIT_ELEMS * 2;
        const uint32_t sBl = sAh + 3 * SPLIT_ELEMS * 2;

        #pragma unroll
        for (int ks = 0; ks < 2; ++ks) {
            uint32_t ah[2][4], alr[2][4], bh[4][4], bl[4][4];
            #pragma unroll
            for (int mi = 0; mi < 2; ++mi) {
                uint32_t off = (uint32_t)((wm * 32 + mi * 16 + a_row) * PITCH
                                          + ks * 16 + a_col) * 2;
                LDSM4(ah[mi],  sAh + off);
                LDSM4(alr[mi], sAl + off);
            }
            #pragma unroll
            for (int jp = 0; jp < 4; ++jp) {
                uint32_t off = (uint32_t)((wn * 64 + jp * 16 + b_row) * PITCH
                                          + ks * 16 + b_col) * 2;
                LDSM4(bh[jp], sBh + off);
                LDSM4(bl[jp], sBl + off);
            }
            #pragma unroll
            for (int mi = 0; mi < 2; ++mi)
                #pragma unroll
                for (int nt = 0; nt < 8; ++nt) {
                    const int jp = nt >> 1, q = (nt & 1) * 2;
                    MMA16816(c[mi][nt], ah[mi],  bh[jp][q], bh[jp][q + 1]);
                    MMA16816(c[mi][nt], ah[mi],  bl[jp][q], bl[jp][q + 1]);
                    MMA16816(c[mi][nt], alr[mi], bh[jp][q], bh[jp][q + 1]);
                }
        }
        __syncthreads();
        if (ch + 2 < 32) stage_load(ch & 1, (ch + 2) * 32);
    }

    const int rbase = m0 + wm * 32 + (lane >> 2);
    const int cpair = (lane & 3) * 2;

    if (mode == 0) {
        const int which = n0 >> 10;
        __nv_bfloat16 *dh, *dl;
        if (which == 0)      { dh = qh; dl = ql; }
        else if (which == 1) { dh = kh; dl = kl; }
        else                 { dh = vh; dl = vl; }
        const float sc = (which == 0) ? SCALE_Q : 1.0f;
        const int h = ((n0 & 1023) >> 6) + wn;
        #pragma unroll
        for (int mi = 0; mi < 2; ++mi) {
            const int m1 = rbase + mi * 16;
            const int m2 = m1 + 8;
            const size_t base1 = (((size_t)(m1 >> 11) * HH + h) * TT + (m1 & 2047)) * DD;
            const size_t base2 = (((size_t)(m2 >> 11) * HH + h) * TT + (m2 & 2047)) * DD;
            #pragma unroll
            for (int nt = 0; nt < 8; ++nt) {
                const int d = nt * 8 + cpair;
                uint32_t h1, l1, h2, l2;
                split2(c[mi][nt][0] * sc, c[mi][nt][1] * sc, h1, l1);
                split2(c[mi][nt][2] * sc, c[mi][nt][3] * sc, h2, l2);
                *(uint32_t*)(dh + base1 + d) = h1;
                *(uint32_t*)(dl + base1 + d) = l1;
                *(uint32_t*)(dh + base2 + d) = h2;
                *(uint32_t*)(dl + base2 + d) = l2;
            }
        }
    } else {
        #pragma unroll
        for (int mi = 0; mi < 2; ++mi) {
            const int m1 = rbase + mi * 16;
            float* r1 = oplain + (size_t)m1 * EE;
            float* r2 = oplain + (size_t)(m1 + 8) * EE;
            #pragma unroll
            for (int nt = 0; nt < 8; ++nt) {
                const int col = n0 + wn * 64 + nt * 8 + cpair;
                const float b0 = bias[col], b1v = bias[col + 1];
                float2 v1 = make_float2(c[mi][nt][0] + b0, c[mi][nt][1] + b1v);
                float2 v2 = make_float2(c[mi][nt][2] + b0, c[mi][nt][3] + b1v);
                *(float2*)(r1 + col) = v1;
                *(float2*)(r2 + col) = v2;
            }
        }
    }
}

// ---------------------------------------------------------------------------
// Tensor-core causal flash attention.
// Block: (bh, qtile of 128 rows), 8 warps, warp = 16 query rows x full tile.
// S = Q.K^T (3-pass split bf16), softmax w/ FMA-pipe exp2, O = P.V (3-pass),
// P A-frags packed directly from S C-frags. K/V tiles cp.async double-buffered.
// ---------------------------------------------------------------------------
#define AP 72                      // smem pitch (bf16 elems), conflict-free ldsm
#define SM_Q 0                     // qh[128*AP], ql[128*AP]
#define QARR (128 * AP * 2)        // 18432 B per array
#define SM_STAGE (2 * QARR)        // 36864
#define KVARR (64 * AP * 2)        // 9216 B per array
#define STAGE_SZ (4 * KVARR)       // kh,kl,vh,vl = 36864
#define SM_MASK (SM_STAGE + 2 * STAGE_SZ)   // 110592
#define SM_TOTAL (SM_MASK + 512)

__global__ __launch_bounds__(256, 1)
void attn_mma(const __nv_bfloat16* __restrict__ qh, const __nv_bfloat16* __restrict__ ql,
              const __nv_bfloat16* __restrict__ kh, const __nv_bfloat16* __restrict__ kl,
              const __nv_bfloat16* __restrict__ vh, const __nv_bfloat16* __restrict__ vl,
              const float* __restrict__ amask, float* __restrict__ ctx)
{
    extern __shared__ char sm[];
    const uint32_t sbase = smem_u32(sm);
    const int tid = threadIdx.x;
    const int w = tid >> 5, lane = tid & 31;
    const int bh = blockIdx.x;
    const int b_ = bh >> 4, h = bh & 15;
    const int qt = 15 - blockIdx.y;          // big tiles first
    const int q0 = qt * 128;
    const int last = 2 * qt + 1;

    const int a_row = lane & 15;
    const int a_col = (lane >> 4) << 3;
    const int b_row = ((lane >> 4) << 3) + (lane & 7);
    const int b_col = ((lane >> 3) & 1) << 3;
    const int v_key = (lane & 7) + (((lane >> 3) & 1) << 3);
    const int v_d   = (lane >> 4) << 3;

    const size_t gbase = (size_t)bh * TT * DD;

    // ---- loaders ----
    auto load_q = [&]() {
        #pragma unroll
        for (int arr = 0; arr < 2; ++arr) {
            const __nv_bfloat16* src0 = arr ? ql : qh;
            #pragma unroll
            for (int half = 0; half < 4; ++half) {
                int loc = half * 256 + tid;          // 0..1023
                int r = loc >> 3, seg = loc & 7;
                const __nv_bfloat16* src = src0 + gbase + (size_t)(q0 + r) * DD + seg * 8;
                uint32_t dst = sbase + SM_Q + arr * QARR + (uint32_t)(r * AP + seg * 8) * 2;
                CP_ASYNC16(dst, src);
            }
        }
    };
    auto load_kv = [&](int buf, int kt) {
        const int s0 = kt * 64;
        #pragma unroll
        for (int arr = 0; arr < 4; ++arr) {
            const __nv_bfloat16* src0 = (arr == 0) ? kh : (arr == 1) ? kl
                                       : (arr == 2) ? vh : vl;
            #pragma unroll
            for (int half = 0; half < 2; ++half) {
                int loc = half * 256 + tid;          // 0..511
                int r = loc >> 3, seg = loc & 7;
                const __nv_bfloat16* src = src0 + gbase + (size_t)(s0 + r) * DD + seg * 8;
                uint32_t dst = sbase + SM_STAGE + buf * STAGE_SZ + arr * KVARR
                             + (uint32_t)(r * AP + seg * 8) * 2;
                CP_ASYNC16(dst, src);
            }
        }
        if (tid < 16) {
            const float* msrc = amask + (size_t)b_ * TT + s0 + tid * 4;
            uint32_t mdst = sbase + SM_MASK + buf * 256 + tid * 16;
            CP_ASYNC16(mdst, msrc);
        }
    };

    load_q();
    load_kv(0, 0);
    CP_COMMIT();
    load_kv(1, 1);
    CP_COMMIT();
    asm volatile("cp.async.wait_group 1;" ::: "memory");
    __syncthreads();

    // Q fragments (persistent)
    uint32_t qa_h[4][4], qa_l[4][4];
    #pragma unroll
    for (int ks = 0; ks < 4; ++ks) {
        uint32_t off = (uint32_t)((w * 16 + a_row) * AP + ks * 16 + a_col) * 2;
        LDSM4(qa_h[ks], sbase + SM_Q + off);
        LDSM4(qa_l[ks], sbase + SM_Q + QARR + off);
    }

    float o[8][4] = {};
    float m0r = -1e30f, m1r = -1e30f, l0 = 0.f, l1 = 0.f;
    const int row0 = q0 + w * 16 + (lane >> 2);
    const int wrow_hi = q0 + w * 16 + 15;     // max row this warp owns

    for (int kt = 0; kt <= last; ++kt) {
        const int buf = kt & 1;
        const int s0 = kt * 64;
        const bool active = (s0 <= wrow_hi);   // any unmasked col for this warp?

        if (active) {
            const uint32_t kb = sbase + SM_STAGE + buf * STAGE_SZ;
            // ---- S = Q.K^T ----
            float c[8][4] = {};
            #pragma unroll
            for (int ks = 0; ks < 4; ++ks) {
                uint32_t kbh[4][4], kbl[4][4];
                #pragma unroll
                for (int jp = 0; jp < 4; ++jp) {
                    uint32_t off = (uint32_t)((jp * 16 + b_row) * AP + ks * 16 + b_col) * 2;
                    LDSM4(kbh[jp], kb + off);
                    LDSM4(kbl[jp], kb + KVARR + off);
                }
                #pragma unroll
                for (int nt = 0; nt < 8; ++nt) {
                    const int jp = nt >> 1, q = (nt & 1) * 2;
                    MMA16816(c[nt], qa_h[ks], kbh[jp][q], kbh[jp][q + 1]);
                    MMA16816(c[nt], qa_h[ks], kbl[jp][q], kbl[jp][q + 1]);
                    MMA16816(c[nt], qa_l[ks], kbh[jp][q], kbh[jp][q + 1]);
                }
            }
            // ---- mask + causal ----
            const float* mk = (const float*)(sm + SM_MASK + buf * 256);
            const bool dg = (s0 + 63) > (q0 + w * 16);
            #pragma unroll
            for (int nt = 0; nt < 8; ++nt) {
                const int cl = nt * 8 + (lane & 3) * 2;
                const float mv0 = mk[cl], mv1 = mk[cl + 1];
                const float ma0 = (1.0f - mv0) * -1e30f;
                const float ma1 = (1.0f - mv1) * -1e30f;
                c[nt][0] += ma0; c[nt][1] += ma1;
                c[nt][2] += ma0; c[nt][3] += ma1;
                if (dg) {
                    const int cg = s0 + cl;
                    if (cg     > row0)     c[nt][0] = -1e30f;
                    if (cg + 1 > row0)     c[nt][1] = -1e30f;
                    if (cg     > row0 + 8) c[nt][2] = -1e30f;
                    if (cg + 1 > row0 + 8) c[nt][3] = -1e30f;
                }
            }
            // ---- online softmax (log2 domain; scale folded into q) ----
            float t0 = -1e30f, t1 = -1e30f;
            #pragma unroll
            for (int nt = 0; nt < 8; ++nt) {
                t0 = fmaxf(t0, fmaxf(c[nt][0], c[nt][1]));
                t1 = fmaxf(t1, fmaxf(c[nt][2], c[nt][3]));
            }
            t0 = fmaxf(t0, __shfl_xor_sync(0xffffffffu, t0, 1));
            t0 = fmaxf(t0, __shfl_xor_sync(0xffffffffu, t0, 2));
            t1 = fmaxf(t1, __shfl_xor_sync(0xffffffffu, t1, 1));
            t1 = fmaxf(t1, __shfl_xor_sync(0xffffffffu, t1, 2));
            const float mn0 = fmaxf(m0r, t0), mn1 = fmaxf(m1r, t1);
            const float cor0 = exp2fast(m0r - mn0), cor1 = exp2fast(m1r - mn1);
            m0r = mn0; m1r = mn1;
            l0 *= cor0; l1 *= cor1;
            #pragma unroll
            for (int nt = 0; nt < 8; ++nt) {
                o[nt][0] *= cor0; o[nt][1] *= cor0;
                o[nt][2] *= cor1; o[nt][3] *= cor1;
            }
            // ---- p = 2^(s-m), pack into PV A-frags, row sums ----
            uint32_t pah[4][4], pal[4][4];
            float s0sum = 0.f, s1sum = 0.f;
            #pragma unroll
            for (int nt = 0; nt < 8; ++nt) {
                const float p0 = exp2fast(c[nt][0] - mn0);
                const float p1 = exp2fast(c[nt][1] - mn0);
                const float p2 = exp2fast(c[nt][2] - mn1);
                const float p3 = exp2fast(c[nt][3] - mn1);
                s0sum += p0 + p1; s1sum += p2 + p3;
                const int ks = nt >> 1;
                const int base = (nt & 1) * 2;
                split2(p0, p1, pah[ks][base], pal[ks][base]);
                split2(p2, p3, pah[ks][base + 1], pal[ks][base + 1]);
            }
            s0sum += __shfl_xor_sync(0xffffffffu, s0sum, 1);
            s0sum += __shfl_xor_sync(0xffffffffu, s0sum, 2);
            s1sum += __shfl_xor_sync(0xffffffffu, s1sum, 1);
            s1sum += __shfl_xor_sync(0xffffffffu, s1sum, 2);
            l0 += s0sum; l1 += s1sum;
            // ---- O += P.V (V via ldmatrix.trans: B = V^T) ----
            #pragma unroll
            for (int ks = 0; ks < 4; ++ks) {
                uint32_t vbh[4][4], vbl[4][4];
                #pragma unroll
                for (int jp = 0; jp < 4; ++jp) {
                    uint32_t off = (uint32_t)((ks * 16 + v_key) * AP + jp * 16 + v_d) * 2;
                    LDSM4T(vbh[jp], kb + 2 * KVARR + off);
                    LDSM4T(vbl[jp], kb + 3 * KVARR + off);
                }
                #pragma unroll
                for (int nt = 0; nt < 8; ++nt) {
                    const int jp = nt >> 1, q = (nt & 1) * 2;
                    MMA16816(o[nt], pah[ks], vbh[jp][q], vbh[jp][q + 1]);
                    MMA16816(o[nt], pah[ks], vbl[jp][q], vbl[jp][q + 1]);
                    MMA16816(o[nt], pal[ks], vbh[jp][q], vbh[jp][q + 1]);
                }
            }
        }
        __syncthreads();
        if (kt + 2 <= last) { load_kv(buf, kt + 2); CP_COMMIT(); }
        if (kt < last) {
            if (kt + 2 <= last) asm volatile("cp.async.wait_group 1;" ::: "memory");
            else                asm volatile("cp.async.wait_group 0;" ::: "memory");
            __syncthreads();
        }
    }

    // ---- normalize + store ctx [B,T,E] ----
    const float inv0 = 1.0f / l0, inv1 = 1.0f / l1;
    const int cpair = (lane & 3) * 2;
    float* r1 = ctx + ((size_t)b_ * TT + row0) * EE + h * 64;
    float* r2 = ctx + ((size_t)b_ * TT + row0 + 8) * EE + h * 64;
    #pragma unroll
    for (int nt = 0; nt < 8; ++nt) {
        const int d = nt * 8 + cpair;
        *(float2*)(r1 + d) = make_float2(o[nt][0] * inv0, o[nt][1] * inv0);
        *(float2*)(r2 + d) = make_float2(o[nt][2] * inv1, o[nt][3] * inv1);
    }
}

// ---------------------------------------------------------------------------
// Launch
// ---------------------------------------------------------------------------
extern "C" void kernel_launch(void* const* d_in, const int* in_sizes, int n_in,
                              void* d_out, int out_size)
{
    const float* x     = (const float*)d_in[0];
    const float* amask = (const float*)d_in[1];
    const float* Wq    = (const float*)d_in[2];
    const float* Wk    = (const float*)d_in[3];
    const float* Wv    = (const float*)d_in[4];
    const float* Wo    = (const float*)d_in[5];
    const float* bo    = (const float*)d_in[6];
    float* out = (float*)d_out;

    float* ctx;
    __nv_bfloat16 *xhi, *xlo, *wth, *wtl, *woh, *wol, *chi, *clo;
    __nv_bfloat16 *qh, *ql, *kh, *kl, *vh, *vl;
    cudaGetSymbolAddress((void**)&ctx, g_ctx);
    cudaGetSymbolAddress((void**)&xhi, g_xhi);
    cudaGetSymbolAddress((void**)&xlo, g_xlo);
    cudaGetSymbolAddress((void**)&wth, g_wth);
    cudaGetSymbolAddress((void**)&wtl, g_wtl);
    cudaGetSymbolAddress((void**)&woh, g_woh);
    cudaGetSymbolAddress((void**)&wol, g_wol);
    cudaGetSymbolAddress((void**)&chi, g_chi);
    cudaGetSymbolAddress((void**)&clo, g_clo);
    cudaGetSymbolAddress((void**)&qh,  g_qh);
    cudaGetSymbolAddress((void**)&ql,  g_ql);
    cudaGetSymbolAddress((void**)&kh,  g_kh);
    cudaGetSymbolAddress((void**)&kl,  g_kl);
    cudaGetSymbolAddress((void**)&vh,  g_vh);
    cudaGetSymbolAddress((void**)&vl,  g_vl);

    cudaFuncSetAttribute(mma_gemm, cudaFuncAttributeMaxDynamicSharedMemorySize,
                         2 * STAGE_BYTES);
    cudaFuncSetAttribute(attn_mma, cudaFuncAttributeMaxDynamicSharedMemorySize,
                         SM_TOTAL);

    conv_hilo<<<(BT * EE / 4) / 256, 256>>>(x, xhi, xlo, BT * EE / 4);
    prep_wt<<<768, 256>>>(Wq, Wk, Wv, wth, wtl);
    conv_hilo<<<(EE * EE / 4) / 256, 256>>>(Wo, woh, wol, EE * EE / 4);

    {   // QKV projection -> bf16 hi/lo q,k,v
        dim3 grid(NQKV / 128, BT / 128);
        mma_gemm<<<grid, 256, 2 * STAGE_BYTES>>>(xhi, xlo, wth, wtl, nullptr,
                                                 qh, ql, kh, kl, vh, vl,
                                                 nullptr, 0);
    }
    {   // attention
        dim3 grid(BB * HH, TT / 128);
        attn_mma<<<grid, 256, SM_TOTAL>>>(qh, ql, kh, kl, vh, vl, amask, ctx);
    }
    conv_hilo<<<(BT * EE / 4) / 256, 256>>>(ctx, chi, clo, BT * EE / 4);
    {   // output projection
        dim3 grid(EE / 128, BT / 128);
        mma_gemm<<<grid, 256, 2 * STAGE_BYTES>>>(chi, clo, woh, wol, bo,
                                                 nullptr, nullptr, nullptr,
                                                 nullptr, nullptr, nullptr,
                                                 out, 1);
    }
}

// round 5
// speedup vs baseline: 3.1906x; 1.0026x over previous
#include <cuda_runtime.h>
#include <cuda_bf16.h>
#include <math_constants.h>
#include <cstdint>

// Problem constants
#define BB 4
#define TT 2048
#define EE 1024
#define HH 16
#define DD 64
#define BT (BB*TT)          // 8192
#define NQKV 3072

#define L2E 1.44269504f
#define SCALE_Q (0.125f * L2E)    // fold 1/sqrt(D) and log2(e) into q

// ---------------------------------------------------------------------------
// Scratch (allocation-free rule: __device__ globals)
// ---------------------------------------------------------------------------
__device__ __align__(16) float g_ctx[(size_t)BB*TT*EE];     // [B,T,H*D]

__device__ __align__(16) __nv_bfloat16 g_xhi[(size_t)BT*EE];
__device__ __align__(16) __nv_bfloat16 g_xlo[(size_t)BT*EE];
__device__ __align__(16) __nv_bfloat16 g_wth[(size_t)NQKV*EE];
__device__ __align__(16) __nv_bfloat16 g_wtl[(size_t)NQKV*EE];
__device__ __align__(16) __nv_bfloat16 g_woh[(size_t)EE*EE];
__device__ __align__(16) __nv_bfloat16 g_wol[(size_t)EE*EE];
__device__ __align__(16) __nv_bfloat16 g_chi[(size_t)BT*EE];
__device__ __align__(16) __nv_bfloat16 g_clo[(size_t)BT*EE];

// bf16 hi/lo q,k,v in [B,H,T,D]
__device__ __align__(16) __nv_bfloat16 g_qh[(size_t)BB*HH*TT*DD];
__device__ __align__(16) __nv_bfloat16 g_ql[(size_t)BB*HH*TT*DD];
__device__ __align__(16) __nv_bfloat16 g_kh[(size_t)BB*HH*TT*DD];
__device__ __align__(16) __nv_bfloat16 g_kl[(size_t)BB*HH*TT*DD];
__device__ __align__(16) __nv_bfloat16 g_vh[(size_t)BB*HH*TT*DD];
__device__ __align__(16) __nv_bfloat16 g_vl[(size_t)BB*HH*TT*DD];

// ---------------------------------------------------------------------------
// Helpers (base sm_103 ISA: mma.sync / ldmatrix / cp.async)
// ---------------------------------------------------------------------------
__device__ __forceinline__ uint32_t smem_u32(const void* p) {
    uint32_t a;
    asm("{ .reg .u64 t; cvta.to.shared.u64 t, %1; cvt.u32.u64 %0, t; }"
        : "=r"(a) : "l"(p));
    return a;
}

#define LDSM4(r, addr) \
    asm volatile("ldmatrix.sync.aligned.m8n8.x4.shared.b16 {%0,%1,%2,%3}, [%4];" \
        : "=r"((r)[0]), "=r"((r)[1]), "=r"((r)[2]), "=r"((r)[3]) : "r"(addr))

#define LDSM4T(r, addr) \
    asm volatile("ldmatrix.sync.aligned.m8n8.x4.trans.shared.b16 {%0,%1,%2,%3}, [%4];" \
        : "=r"((r)[0]), "=r"((r)[1]), "=r"((r)[2]), "=r"((r)[3]) : "r"(addr))

#define MMA16816(c, a, b0, b1) \
    asm volatile("mma.sync.aligned.m16n8k16.row.col.f32.bf16.bf16.f32 " \
        "{%0,%1,%2,%3}, {%4,%5,%6,%7}, {%8,%9}, {%0,%1,%2,%3};" \
        : "+f"((c)[0]), "+f"((c)[1]), "+f"((c)[2]), "+f"((c)[3]) \
        : "r"((a)[0]), "r"((a)[1]), "r"((a)[2]), "r"((a)[3]), "r"(b0), "r"(b1))

#define CP_ASYNC16(dst, src) \
    asm volatile("cp.async.cg.shared.global [%0], [%1], 16;" :: "r"(dst), "l"(src))
#define CP_COMMIT() asm volatile("cp.async.commit_group;" ::: "memory")

// split two floats into packed bf16x2 hi and lo residual
__device__ __forceinline__ void split2(float a, float b, uint32_t& hi, uint32_t& lo) {
    __nv_bfloat16 ha = __float2bfloat16(a), hb = __float2bfloat16(b);
    float ra = a - __bfloat162float(ha);
    float rb = b - __bfloat162float(hb);
    __nv_bfloat162 H; H.x = ha; H.y = hb;
    __nv_bfloat162 L; L.x = __float2bfloat16(ra); L.y = __float2bfloat16(rb);
    hi = *(uint32_t*)&H;
    lo = *(uint32_t*)&L;
}

// fast exp2 on the FMA pipe (degree-7, rel err ~1e-6)
__device__ __forceinline__ float exp2fast(float x) {
    x = fmaxf(x, -125.0f);
    int n = __float2int_rd(x);
    float f = x - (float)n;
    float p = 1.3570247e-5f;
    p = fmaf(p, f, 1.5353362e-4f);
    p = fmaf(p, f, 1.3398874e-3f);
    p = fmaf(p, f, 9.6184374e-3f);
    p = fmaf(p, f, 5.5503325e-2f);
    p = fmaf(p, f, 2.4022648e-1f);
    p = fmaf(p, f, 6.9314720e-1f);
    p = fmaf(p, f, 1.0f);
    return p * __int_as_float((n + 127) << 23);
}

// ---------------------------------------------------------------------------
// Prep: fp32 -> (bf16 hi, bf16 lo)
// ---------------------------------------------------------------------------
__global__ __launch_bounds__(256) void conv_hilo(
    const float* __restrict__ s, __nv_bfloat16* __restrict__ hi,
    __nv_bfloat16* __restrict__ lo, int n4)
{
    int i = blockIdx.x * 256 + threadIdx.x;
    if (i >= n4) return;
    float4 v = ((const float4*)s)[i];
    uint32_t h0, l0, h1, l1;
    split2(v.x, v.y, h0, l0);
    split2(v.z, v.w, h1, l1);
    ((uint32_t*)hi)[i * 2 + 0] = h0;
    ((uint32_t*)hi)[i * 2 + 1] = h1;
    ((uint32_t*)lo)[i * 2 + 0] = l0;
    ((uint32_t*)lo)[i * 2 + 1] = l1;
}

// ---------------------------------------------------------------------------
// Prep: transpose+split qkv weights. W[h][e][d] -> Wt[n][e]
// ---------------------------------------------------------------------------
__global__ __launch_bounds__(256) void prep_wt(
    const float* __restrict__ Wq, const float* __restrict__ Wk,
    const float* __restrict__ Wv,
    __nv_bfloat16* __restrict__ th, __nv_bfloat16* __restrict__ tl)
{
    __shared__ float ts[64][65];
    const int bx = blockIdx.x;
    const int mi = bx >> 8;
    const int rem = bx & 255;
    const int h = rem >> 4;
    const int e0 = (rem & 15) * 64;
    const float* src = (mi == 0 ? Wq : (mi == 1 ? Wk : Wv)) + (size_t)h * EE * DD;
    const int tid = threadIdx.x;

    #pragma unroll
    for (int i = 0; i < 4; ++i) {
        int idx = tid + i * 256;
        int ei = idx >> 4, d4 = idx & 15;
        float4 v = ((const float4*)(src + (size_t)(e0 + ei) * DD))[d4];
        ts[ei][d4 * 4 + 0] = v.x; ts[ei][d4 * 4 + 1] = v.y;
        ts[ei][d4 * 4 + 2] = v.z; ts[ei][d4 * 4 + 3] = v.w;
    }
    __syncthreads();

    const int d = tid >> 2, seg = tid & 3;
    const size_t row = ((size_t)mi * 1024 + h * 64 + d) * EE + e0 + seg * 16;
    alignas(16) __nv_bfloat16 hb[16], lb[16];
    #pragma unroll
    for (int i = 0; i < 16; ++i) {
        float v = ts[seg * 16 + i][d];
        __nv_bfloat16 hv = __float2bfloat16(v);
        hb[i] = hv;
        lb[i] = __float2bfloat16(v - __bfloat162float(hv));
    }
    *(uint4*)(th + row)     = *(const uint4*)(hb);
    *(uint4*)(th + row + 8) = *(const uint4*)(hb + 8);
    *(uint4*)(tl + row)     = *(const uint4*)(lb);
    *(uint4*)(tl + row + 8) = *(const uint4*)(lb + 8);
}

// ---------------------------------------------------------------------------
// HMMA split-bf16 GEMM. Pass loop OUTERMOST: 16 independent accumulators
// between dependent HMMAs (asm volatile order is final — this is the fix).
// ---------------------------------------------------------------------------
#define PITCH 40
#define SPLIT_ELEMS (128 * PITCH)
#define STAGE_BYTES (4 * SPLIT_ELEMS * 2)

__global__ __launch_bounds__(256, 1)
void mma_gemm(const __nv_bfloat16* __restrict__ Ah, const __nv_bfloat16* __restrict__ Al,
              const __nv_bfloat16* __restrict__ Bh, const __nv_bfloat16* __restrict__ Bl,
              const float* __restrict__ bias,
              __nv_bfloat16* __restrict__ qh, __nv_bfloat16* __restrict__ ql,
              __nv_bfloat16* __restrict__ kh, __nv_bfloat16* __restrict__ kl,
              __nv_bfloat16* __restrict__ vh, __nv_bfloat16* __restrict__ vl,
              float* __restrict__ oplain, int mode)
{
    extern __shared__ char sm[];
    const uint32_t sbase = smem_u32(sm);
    const int tid = threadIdx.x;
    const int wid = tid >> 5, lane = tid & 31;
    const int wm = wid & 3, wn = wid >> 2;
    const int n0 = blockIdx.x * 128;
    const int m0 = blockIdx.y * 128;

    const int a_row = lane & 15;
    const int a_col = (lane >> 4) << 3;
    const int b_row = ((lane >> 4) << 3) + (lane & 7);
    const int b_col = ((lane >> 3) & 1) << 3;

    float c[2][8][4] = {};

    auto stage_load = [&](int buf, int k0) {
        #pragma unroll
        for (int t = 0; t < 8; ++t) {
            const int arr = t >> 1;
            const int local = ((t & 1) << 8) + tid;
            const int r = local >> 2, seg = local & 3;
            const __nv_bfloat16* gb =
                (arr == 0) ? Ah : (arr == 1) ? Al : (arr == 2) ? Bh : Bl;
            const int row0 = (arr < 2) ? m0 : n0;
            const __nv_bfloat16* g = gb + (size_t)(row0 + r) * EE + k0 + seg * 8;
            uint32_t dst = sbase + buf * STAGE_BYTES
                         + (uint32_t)(arr * SPLIT_ELEMS + r * PITCH + seg * 8) * 2;
            CP_ASYNC16(dst, g);
        }
        CP_COMMIT();
    };

    stage_load(0, 0);
    stage_load(1, 32);

    for (int ch = 0; ch < 32; ++ch) {
        if (ch < 31) asm volatile("cp.async.wait_group 1;" ::: "memory");
        else         asm volatile("cp.async.wait_group 0;" ::: "memory");
        __syncthreads();

        const uint32_t sAh = sbase + (ch & 1) * STAGE_BYTES;
        const uint32_t sAl = sAh + SPLIT_ELEMS * 2;
        const uint32_t sBh = sAh + 2 * SPLIT_ELEMS * 2;
        const uint32_t sBl = sAh + 3 * SPLIT_ELEMS * 2;

        #pragma unroll
        for (int ks = 0; ks < 2; ++ks) {
            uint32_t ah[2][4], alr[2][4], bh[4][4], bl[4][4];
            #pragma unroll
            for (int mi = 0; mi < 2; ++mi) {
                uint32_t off = (uint32_t)((wm * 32 + mi * 16 + a_row) * PITCH
                                          + ks * 16 + a_col) * 2;
                LDSM4(ah[mi],  sAh + off);
                LDSM4(alr[mi], sAl + off);
            }
            #pragma unroll
            for (int jp = 0; jp < 4; ++jp) {
                uint32_t off = (uint32_t)((wn * 64 + jp * 16 + b_row) * PITCH
                                          + ks * 16 + b_col) * 2;
                LDSM4(bh[jp], sBh + off);
                LDSM4(bl[jp], sBl + off);
            }
            // pass-outer: dependent HMMAs on the same accumulator are 16 apart
            #pragma unroll
            for (int p = 0; p < 3; ++p)
                #pragma unroll
                for (int mi = 0; mi < 2; ++mi)
                    #pragma unroll
                    for (int nt = 0; nt < 8; ++nt) {
                        const int jp = nt >> 1, q = (nt & 1) * 2;
                        if (p == 0)
                            MMA16816(c[mi][nt], ah[mi],  bh[jp][q], bh[jp][q + 1]);
                        else if (p == 1)
                            MMA16816(c[mi][nt], ah[mi],  bl[jp][q], bl[jp][q + 1]);
                        else
                            MMA16816(c[mi][nt], alr[mi], bh[jp][q], bh[jp][q + 1]);
                    }
        }
        __syncthreads();
        if (ch + 2 < 32) stage_load(ch & 1, (ch + 2) * 32);
    }

    const int rbase = m0 + wm * 32 + (lane >> 2);
    const int cpair = (lane & 3) * 2;

    if (mode == 0) {
        const int which = n0 >> 10;
        __nv_bfloat16 *dh, *dl;
        if (which == 0)      { dh = qh; dl = ql; }
        else if (which == 1) { dh = kh; dl = kl; }
        else                 { dh = vh; dl = vl; }
        const float sc = (which == 0) ? SCALE_Q : 1.0f;
        const int h = ((n0 & 1023) >> 6) + wn;
        #pragma unroll
        for (int mi = 0; mi < 2; ++mi) {
            const int m1 = rbase + mi * 16;
            const int m2 = m1 + 8;
            const size_t base1 = (((size_t)(m1 >> 11) * HH + h) * TT + (m1 & 2047)) * DD;
            const size_t base2 = (((size_t)(m2 >> 11) * HH + h) * TT + (m2 & 2047)) * DD;
            #pragma unroll
            for (int nt = 0; nt < 8; ++nt) {
                const int d = nt * 8 + cpair;
                uint32_t h1, l1, h2, l2;
                split2(c[mi][nt][0] * sc, c[mi][nt][1] * sc, h1, l1);
                split2(c[mi][nt][2] * sc, c[mi][nt][3] * sc, h2, l2);
                *(uint32_t*)(dh + base1 + d) = h1;
                *(uint32_t*)(dl + base1 + d) = l1;
                *(uint32_t*)(dh + base2 + d) = h2;
                *(uint32_t*)(dl + base2 + d) = l2;
            }
        }
    } else {
        #pragma unroll
        for (int mi = 0; mi < 2; ++mi) {
            const int m1 = rbase + mi * 16;
            float* r1 = oplain + (size_t)m1 * EE;
            float* r2 = oplain + (size_t)(m1 + 8) * EE;
            #pragma unroll
            for (int nt = 0; nt < 8; ++nt) {
                const int col = n0 + wn * 64 + nt * 8 + cpair;
                const float b0 = bias[col], b1v = bias[col + 1];
                float2 v1 = make_float2(c[mi][nt][0] + b0, c[mi][nt][1] + b1v);
                float2 v2 = make_float2(c[mi][nt][2] + b0, c[mi][nt][3] + b1v);
                *(float2*)(r1 + col) = v1;
                *(float2*)(r2 + col) = v2;
            }
        }
    }
}

// ---------------------------------------------------------------------------
// Tensor-core causal flash attention (pass-outer MMA issue order).
// ---------------------------------------------------------------------------
#define AP 72
#define SM_Q 0
#define QARR (128 * AP * 2)
#define SM_STAGE (2 * QARR)
#define KVARR (64 * AP * 2)
#define STAGE_SZ (4 * KVARR)
#define SM_MASK (SM_STAGE + 2 * STAGE_SZ)
#define SM_TOTAL (SM_MASK + 512)

__global__ __launch_bounds__(256, 1)
void attn_mma(const __nv_bfloat16* __restrict__ qh, const __nv_bfloat16* __restrict__ ql,
              const __nv_bfloat16* __restrict__ kh, const __nv_bfloat16* __restrict__ kl,
              const __nv_bfloat16* __restrict__ vh, const __nv_bfloat16* __restrict__ vl,
              const float* __restrict__ amask, float* __restrict__ ctx)
{
    extern __shared__ char sm[];
    const uint32_t sbase = smem_u32(sm);
    const int tid = threadIdx.x;
    const int w = tid >> 5, lane = tid & 31;
    const int bh = blockIdx.x;
    const int b_ = bh >> 4, h = bh & 15;
    const int qt = 15 - blockIdx.y;
    const int q0 = qt * 128;
    const int last = 2 * qt + 1;

    const int a_row = lane & 15;
    const int a_col = (lane >> 4) << 3;
    const int b_row = ((lane >> 4) << 3) + (lane & 7);
    const int b_col = ((lane >> 3) & 1) << 3;
    const int v_key = (lane & 7) + (((lane >> 3) & 1) << 3);
    const int v_d   = (lane >> 4) << 3;

    const size_t gbase = (size_t)bh * TT * DD;

    auto load_q = [&]() {
        #pragma unroll
        for (int arr = 0; arr < 2; ++arr) {
            const __nv_bfloat16* src0 = arr ? ql : qh;
            #pragma unroll
            for (int half = 0; half < 4; ++half) {
                int loc = half * 256 + tid;
                int r = loc >> 3, seg = loc & 7;
                const __nv_bfloat16* src = src0 + gbase + (size_t)(q0 + r) * DD + seg * 8;
                uint32_t dst = sbase + SM_Q + arr * QARR + (uint32_t)(r * AP + seg * 8) * 2;
                CP_ASYNC16(dst, src);
            }
        }
    };
    auto load_kv = [&](int buf, int kt) {
        const int s0 = kt * 64;
        #pragma unroll
        for (int arr = 0; arr < 4; ++arr) {
            const __nv_bfloat16* src0 = (arr == 0) ? kh : (arr == 1) ? kl
                                       : (arr == 2) ? vh : vl;
            #pragma unroll
            for (int half = 0; half < 2; ++half) {
                int loc = half * 256 + tid;
                int r = loc >> 3, seg = loc & 7;
                const __nv_bfloat16* src = src0 + gbase + (size_t)(s0 + r) * DD + seg * 8;
                uint32_t dst = sbase + SM_STAGE + buf * STAGE_SZ + arr * KVARR
                             + (uint32_t)(r * AP + seg * 8) * 2;
                CP_ASYNC16(dst, src);
            }
        }
        if (tid < 16) {
            const float* msrc = amask + (size_t)b_ * TT + s0 + tid * 4;
            uint32_t mdst = sbase + SM_MASK + buf * 256 + tid * 16;
            CP_ASYNC16(mdst, msrc);
        }
    };

    load_q();
    load_kv(0, 0);
    CP_COMMIT();
    load_kv(1, 1);
    CP_COMMIT();
    asm volatile("cp.async.wait_group 1;" ::: "memory");
    __syncthreads();

    uint32_t qa_h[4][4], qa_l[4][4];
    #pragma unroll
    for (int ks = 0; ks < 4; ++ks) {
        uint32_t off = (uint32_t)((w * 16 + a_row) * AP + ks * 16 + a_col) * 2;
        LDSM4(qa_h[ks], sbase + SM_Q + off);
        LDSM4(qa_l[ks], sbase + SM_Q + QARR + off);
    }

    float o[8][4] = {};
    float m0r = -1e30f, m1r = -1e30f, l0 = 0.f, l1 = 0.f;
    const int row0 = q0 + w * 16 + (lane >> 2);
    const int wrow_hi = q0 + w * 16 + 15;

    for (int kt = 0; kt <= last; ++kt) {
        const int buf = kt & 1;
        const int s0 = kt * 64;
        const bool active = (s0 <= wrow_hi);

        if (active) {
            const uint32_t kb = sbase + SM_STAGE + buf * STAGE_SZ;
            // ---- S = Q.K^T (pass-outer issue) ----
            float c[8][4] = {};
            #pragma unroll
            for (int ks = 0; ks < 4; ++ks) {
                uint32_t kbh[4][4], kbl[4][4];
                #pragma unroll
                for (int jp = 0; jp < 4; ++jp) {
                    uint32_t off = (uint32_t)((jp * 16 + b_row) * AP + ks * 16 + b_col) * 2;
                    LDSM4(kbh[jp], kb + off);
                    LDSM4(kbl[jp], kb + KVARR + off);
                }
                #pragma unroll
                for (int p = 0; p < 3; ++p)
                    #pragma unroll
                    for (int nt = 0; nt < 8; ++nt) {
                        const int jp = nt >> 1, q = (nt & 1) * 2;
                        if (p == 0)
                            MMA16816(c[nt], qa_h[ks], kbh[jp][q], kbh[jp][q + 1]);
                        else if (p == 1)
                            MMA16816(c[nt], qa_h[ks], kbl[jp][q], kbl[jp][q + 1]);
                        else
                            MMA16816(c[nt], qa_l[ks], kbh[jp][q], kbh[jp][q + 1]);
                    }
            }
            // ---- mask + causal ----
            const float* mk = (const float*)(sm + SM_MASK + buf * 256);
            const bool dg = (s0 + 63) > (q0 + w * 16);
            #pragma unroll
            for (int nt = 0; nt < 8; ++nt) {
                const int cl = nt * 8 + (lane & 3) * 2;
                const float mv0 = mk[cl], mv1 = mk[cl + 1];
                const float ma0 = (1.0f - mv0) * -1e30f;
                const float ma1 = (1.0f - mv1) * -1e30f;
                c[nt][0] += ma0; c[nt][1] += ma1;
                c[nt][2] += ma0; c[nt][3] += ma1;
                if (dg) {
                    const int cg = s0 + cl;
                    if (cg     > row0)     c[nt][0] = -1e30f;
                    if (cg + 1 > row0)     c[nt][1] = -1e30f;
                    if (cg     > row0 + 8) c[nt][2] = -1e30f;
                    if (cg + 1 > row0 + 8) c[nt][3] = -1e30f;
                }
            }
            // ---- online softmax ----
            float t0 = -1e30f, t1 = -1e30f;
            #pragma unroll
            for (int nt = 0; nt < 8; ++nt) {
                t0 = fmaxf(t0, fmaxf(c[nt][0], c[nt][1]));
                t1 = fmaxf(t1, fmaxf(c[nt][2], c[nt][3]));
            }
            t0 = fmaxf(t0, __shfl_xor_sync(0xffffffffu, t0, 1));
            t0 = fmaxf(t0, __shfl_xor_sync(0xffffffffu, t0, 2));
            t1 = fmaxf(t1, __shfl_xor_sync(0xffffffffu, t1, 1));
            t1 = fmaxf(t1, __shfl_xor_sync(0xffffffffu, t1, 2));
            const float mn0 = fmaxf(m0r, t0), mn1 = fmaxf(m1r, t1);
            const float cor0 = exp2fast(m0r - mn0), cor1 = exp2fast(m1r - mn1);
            m0r = mn0; m1r = mn1;
            l0 *= cor0; l1 *= cor1;
            #pragma unroll
            for (int nt = 0; nt < 8; ++nt) {
                o[nt][0] *= cor0; o[nt][1] *= cor0;
                o[nt][2] *= cor1; o[nt][3] *= cor1;
            }
            // ---- p = 2^(s-m) ----
            uint32_t pah[4][4], pal[4][4];
            float s0sum = 0.f, s1sum = 0.f;
            #pragma unroll
            for (int nt = 0; nt < 8; ++nt) {
                const float p0 = exp2fast(c[nt][0] - mn0);
                const float p1 = exp2fast(c[nt][1] - mn0);
                const float p2 = exp2fast(c[nt][2] - mn1);
                const float p3 = exp2fast(c[nt][3] - mn1);
                s0sum += p0 + p1; s1sum += p2 + p3;
                const int ks = nt >> 1;
                const int base = (nt & 1) * 2;
                split2(p0, p1, pah[ks][base], pal[ks][base]);
                split2(p2, p3, pah[ks][base + 1], pal[ks][base + 1]);
            }
            s0sum += __shfl_xor_sync(0xffffffffu, s0sum, 1);
            s0sum += __shfl_xor_sync(0xffffffffu, s0sum, 2);
            s1sum += __shfl_xor_sync(0xffffffffu, s1sum, 1);
            s1sum += __shfl_xor_sync(0xffffffffu, s1sum, 2);
            l0 += s0sum; l1 += s1sum;
            // ---- O += P.V (pass-outer issue) ----
            #pragma unroll
            for (int ks = 0; ks < 4; ++ks) {
                uint32_t vbh[4][4], vbl[4][4];
                #pragma unroll
                for (int jp = 0; jp < 4; ++jp) {
                    uint32_t off = (uint32_t)((ks * 16 + v_key) * AP + jp * 16 + v_d) * 2;
                    LDSM4T(vbh[jp], kb + 2 * KVARR + off);
                    LDSM4T(vbl[jp], kb + 3 * KVARR + off);
                }
                #pragma unroll
                for (int p = 0; p < 3; ++p)
                    #pragma unroll
                    for (int nt = 0; nt < 8; ++nt) {
                        const int jp = nt >> 1, q = (nt & 1) * 2;
                        if (p == 0)
                            MMA16816(o[nt], pah[ks], vbh[jp][q], vbh[jp][q + 1]);
                        else if (p == 1)
                            MMA16816(o[nt], pah[ks], vbl[jp][q], vbl[jp][q + 1]);
                        else
                            MMA16816(o[nt], pal[ks], vbh[jp][q], vbh[jp][q + 1]);
                    }
            }
        }
        __syncthreads();
        if (kt + 2 <= last) { load_kv(buf, kt + 2); CP_COMMIT(); }
        if (kt < last) {
            if (kt + 2 <= last) asm volatile("cp.async.wait_group 1;" ::: "memory");
            else                asm volatile("cp.async.wait_group 0;" ::: "memory");
            __syncthreads();
        }
    }

    // ---- normalize + store ----
    const float inv0 = 1.0f / l0, inv1 = 1.0f / l1;
    const int cpair = (lane & 3) * 2;
    float* r1 = ctx + ((size_t)b_ * TT + row0) * EE + h * 64;
    float* r2 = ctx + ((size_t)b_ * TT + row0 + 8) * EE + h * 64;
    #pragma unroll
    for (int nt = 0; nt < 8; ++nt) {
        const int d = nt * 8 + cpair;
        *(float2*)(r1 + d) = make_float2(o[nt][0] * inv0, o[nt][1] * inv0);
        *(float2*)(r2 + d) = make_float2(o[nt][2] * inv1, o[nt][3] * inv1);
    }
}

// ---------------------------------------------------------------------------
// Launch
// ---------------------------------------------------------------------------
extern "C" void kernel_launch(void* const* d_in, const int* in_sizes, int n_in,
                              void* d_out, int out_size)
{
    const float* x     = (const float*)d_in[0];
    const float* amask = (const float*)d_in[1];
    const float* Wq    = (const float*)d_in[2];
    const float* Wk    = (const float*)d_in[3];
    const float* Wv    = (const float*)d_in[4];
    const float* Wo    = (const float*)d_in[5];
    const float* bo    = (const float*)d_in[6];
    float* out = (float*)d_out;

    float* ctx;
    __nv_bfloat16 *xhi, *xlo, *wth, *wtl, *woh, *wol, *chi, *clo;
    __nv_bfloat16 *qh, *ql, *kh, *kl, *vh, *vl;
    cudaGetSymbolAddress((void**)&ctx, g_ctx);
    cudaGetSymbolAddress((void**)&xhi, g_xhi);
    cudaGetSymbolAddress((void**)&xlo, g_xlo);
    cudaGetSymbolAddress((void**)&wth, g_wth);
    cudaGetSymbolAddress((void**)&wtl, g_wtl);
    cudaGetSymbolAddress((void**)&woh, g_woh);
    cudaGetSymbolAddress((void**)&wol, g_wol);
    cudaGetSymbolAddress((void**)&chi, g_chi);
    cudaGetSymbolAddress((void**)&clo, g_clo);
    cudaGetSymbolAddress((void**)&qh,  g_qh);
    cudaGetSymbolAddress((void**)&ql,  g_ql);
    cudaGetSymbolAddress((void**)&kh,  g_kh);
    cudaGetSymbolAddress((void**)&kl,  g_kl);
    cudaGetSymbolAddress((void**)&vh,  g_vh);
    cudaGetSymbolAddress((void**)&vl,  g_vl);

    cudaFuncSetAttribute(mma_gemm, cudaFuncAttributeMaxDynamicSharedMemorySize,
                         2 * STAGE_BYTES);
    cudaFuncSetAttribute(attn_mma, cudaFuncAttributeMaxDynamicSharedMemorySize,
                         SM_TOTAL);

    conv_hilo<<<(BT * EE / 4) / 256, 256>>>(x, xhi, xlo, BT * EE / 4);
    prep_wt<<<768, 256>>>(Wq, Wk, Wv, wth, wtl);
    conv_hilo<<<(EE * EE / 4) / 256, 256>>>(Wo, woh, wol, EE * EE / 4);

    {   // QKV projection -> bf16 hi/lo q,k,v
        dim3 grid(NQKV / 128, BT / 128);
        mma_gemm<<<grid, 256, 2 * STAGE_BYTES>>>(xhi, xlo, wth, wtl, nullptr,
                                                 qh, ql, kh, kl, vh, vl,
                                                 nullptr, 0);
    }
    {   // attention
        dim3 grid(BB * HH, TT / 128);
        attn_mma<<<grid, 256, SM_TOTAL>>>(qh, ql, kh, kl, vh, vl, amask, ctx);
    }
    conv_hilo<<<(BT * EE / 4) / 256, 256>>>(ctx, chi, clo, BT * EE / 4);
    {   // output projection
        dim3 grid(EE / 128, BT / 128);
        mma_gemm<<<grid, 256, 2 * STAGE_BYTES>>>(chi, clo, woh, wol, bo,
                                                 nullptr, nullptr, nullptr,
                                                 nullptr, nullptr, nullptr,
                                                 out, 1);
    }
}

// round 6
// speedup vs baseline: 3.4709x; 1.0878x over previous
#include <cuda_runtime.h>
#include <cuda_bf16.h>
#include <math_constants.h>
#include <cstdint>

// Problem constants
#define BB 4
#define TT 2048
#define EE 1024
#define HH 16
#define DD 64
#define BT (BB*TT)          // 8192
#define NQKV 3072

#define L2E 1.44269504f
#define SCALE_Q (0.125f * L2E)    // fold 1/sqrt(D) and log2(e) into q

// ---------------------------------------------------------------------------
// Scratch (allocation-free rule: __device__ globals)
// ---------------------------------------------------------------------------
__device__ __align__(16) float g_ctx[(size_t)BB*TT*EE];     // [B,T,H*D]

__device__ __align__(16) __nv_bfloat16 g_xhi[(size_t)BT*EE];
__device__ __align__(16) __nv_bfloat16 g_xlo[(size_t)BT*EE];
__device__ __align__(16) __nv_bfloat16 g_wth[(size_t)NQKV*EE];
__device__ __align__(16) __nv_bfloat16 g_wtl[(size_t)NQKV*EE];
__device__ __align__(16) __nv_bfloat16 g_woh[(size_t)EE*EE];
__device__ __align__(16) __nv_bfloat16 g_wol[(size_t)EE*EE];
__device__ __align__(16) __nv_bfloat16 g_chi[(size_t)BT*EE];
__device__ __align__(16) __nv_bfloat16 g_clo[(size_t)BT*EE];

// bf16 hi/lo q,k,v in [B,H,T,D]
__device__ __align__(16) __nv_bfloat16 g_qh[(size_t)BB*HH*TT*DD];
__device__ __align__(16) __nv_bfloat16 g_ql[(size_t)BB*HH*TT*DD];
__device__ __align__(16) __nv_bfloat16 g_kh[(size_t)BB*HH*TT*DD];
__device__ __align__(16) __nv_bfloat16 g_kl[(size_t)BB*HH*TT*DD];
__device__ __align__(16) __nv_bfloat16 g_vh[(size_t)BB*HH*TT*DD];
__device__ __align__(16) __nv_bfloat16 g_vl[(size_t)BB*HH*TT*DD];

// ---------------------------------------------------------------------------
// Helpers (base sm_103 ISA: mma.sync / ldmatrix / cp.async)
// ---------------------------------------------------------------------------
__device__ __forceinline__ uint32_t smem_u32(const void* p) {
    uint32_t a;
    asm("{ .reg .u64 t; cvta.to.shared.u64 t, %1; cvt.u32.u64 %0, t; }"
        : "=r"(a) : "l"(p));
    return a;
}

#define LDSM4(r, addr) \
    asm volatile("ldmatrix.sync.aligned.m8n8.x4.shared.b16 {%0,%1,%2,%3}, [%4];" \
        : "=r"((r)[0]), "=r"((r)[1]), "=r"((r)[2]), "=r"((r)[3]) : "r"(addr))

#define LDSM4T(r, addr) \
    asm volatile("ldmatrix.sync.aligned.m8n8.x4.trans.shared.b16 {%0,%1,%2,%3}, [%4];" \
        : "=r"((r)[0]), "=r"((r)[1]), "=r"((r)[2]), "=r"((r)[3]) : "r"(addr))

#define MMA16816(c, a, b0, b1) \
    asm volatile("mma.sync.aligned.m16n8k16.row.col.f32.bf16.bf16.f32 " \
        "{%0,%1,%2,%3}, {%4,%5,%6,%7}, {%8,%9}, {%0,%1,%2,%3};" \
        : "+f"((c)[0]), "+f"((c)[1]), "+f"((c)[2]), "+f"((c)[3]) \
        : "r"((a)[0]), "r"((a)[1]), "r"((a)[2]), "r"((a)[3]), "r"(b0), "r"(b1))

#define CP_ASYNC16(dst, src) \
    asm volatile("cp.async.cg.shared.global [%0], [%1], 16;" :: "r"(dst), "l"(src))
#define CP_COMMIT() asm volatile("cp.async.commit_group;" ::: "memory")

// split two floats into packed bf16x2 hi and lo residual
__device__ __forceinline__ void split2(float a, float b, uint32_t& hi, uint32_t& lo) {
    __nv_bfloat16 ha = __float2bfloat16(a), hb = __float2bfloat16(b);
    float ra = a - __bfloat162float(ha);
    float rb = b - __bfloat162float(hb);
    __nv_bfloat162 H; H.x = ha; H.y = hb;
    __nv_bfloat162 L; L.x = __float2bfloat16(ra); L.y = __float2bfloat16(rb);
    hi = *(uint32_t*)&H;
    lo = *(uint32_t*)&L;
}

// fast exp2 on the FMA pipe (degree-7, rel err ~1e-6)
__device__ __forceinline__ float exp2fast(float x) {
    x = fmaxf(x, -125.0f);
    int n = __float2int_rd(x);
    float f = x - (float)n;
    float p = 1.3570247e-5f;
    p = fmaf(p, f, 1.5353362e-4f);
    p = fmaf(p, f, 1.3398874e-3f);
    p = fmaf(p, f, 9.6184374e-3f);
    p = fmaf(p, f, 5.5503325e-2f);
    p = fmaf(p, f, 2.4022648e-1f);
    p = fmaf(p, f, 6.9314720e-1f);
    p = fmaf(p, f, 1.0f);
    return p * __int_as_float((n + 127) << 23);
}

// ---------------------------------------------------------------------------
// Prep: fp32 -> (bf16 hi, bf16 lo)
// ---------------------------------------------------------------------------
__global__ __launch_bounds__(256) void conv_hilo(
    const float* __restrict__ s, __nv_bfloat16* __restrict__ hi,
    __nv_bfloat16* __restrict__ lo, int n4)
{
    int i = blockIdx.x * 256 + threadIdx.x;
    if (i >= n4) return;
    float4 v = ((const float4*)s)[i];
    uint32_t h0, l0, h1, l1;
    split2(v.x, v.y, h0, l0);
    split2(v.z, v.w, h1, l1);
    ((uint32_t*)hi)[i * 2 + 0] = h0;
    ((uint32_t*)hi)[i * 2 + 1] = h1;
    ((uint32_t*)lo)[i * 2 + 0] = l0;
    ((uint32_t*)lo)[i * 2 + 1] = l1;
}

// ---------------------------------------------------------------------------
// Prep: transpose+split qkv weights. W[h][e][d] -> Wt[n][e]
// ---------------------------------------------------------------------------
__global__ __launch_bounds__(256) void prep_wt(
    const float* __restrict__ Wq, const float* __restrict__ Wk,
    const float* __restrict__ Wv,
    __nv_bfloat16* __restrict__ th, __nv_bfloat16* __restrict__ tl)
{
    __shared__ float ts[64][65];
    const int bx = blockIdx.x;
    const int mi = bx >> 8;
    const int rem = bx & 255;
    const int h = rem >> 4;
    const int e0 = (rem & 15) * 64;
    const float* src = (mi == 0 ? Wq : (mi == 1 ? Wk : Wv)) + (size_t)h * EE * DD;
    const int tid = threadIdx.x;

    #pragma unroll
    for (int i = 0; i < 4; ++i) {
        int idx = tid + i * 256;
        int ei = idx >> 4, d4 = idx & 15;
        float4 v = ((const float4*)(src + (size_t)(e0 + ei) * DD))[d4];
        ts[ei][d4 * 4 + 0] = v.x; ts[ei][d4 * 4 + 1] = v.y;
        ts[ei][d4 * 4 + 2] = v.z; ts[ei][d4 * 4 + 3] = v.w;
    }
    __syncthreads();

    const int d = tid >> 2, seg = tid & 3;
    const size_t row = ((size_t)mi * 1024 + h * 64 + d) * EE + e0 + seg * 16;
    alignas(16) __nv_bfloat16 hb[16], lb[16];
    #pragma unroll
    for (int i = 0; i < 16; ++i) {
        float v = ts[seg * 16 + i][d];
        __nv_bfloat16 hv = __float2bfloat16(v);
        hb[i] = hv;
        lb[i] = __float2bfloat16(v - __bfloat162float(hv));
    }
    *(uint4*)(th + row)     = *(const uint4*)(hb);
    *(uint4*)(th + row + 8) = *(const uint4*)(hb + 8);
    *(uint4*)(tl + row)     = *(const uint4*)(lb);
    *(uint4*)(tl + row + 8) = *(const uint4*)(lb + 8);
}

// ---------------------------------------------------------------------------
// HMMA split-bf16 GEMM, 128Mx64N block, warp tile 32x32, 2 CTAs/SM.
// Small tile + reg cap -> 16 warps/SM; unsynchronized CTAs interleave
// LDSM and HMMA phases (the R5 lockstep fix).
// ---------------------------------------------------------------------------
#define PITCH 40
#define A_ELEMS (128 * PITCH)            // 5120
#define B_ELEMS (64 * PITCH)             // 2560
#define STAGE_ELEMS (2 * A_ELEMS + 2 * B_ELEMS)   // 15360
#define STAGE_BYTES (STAGE_ELEMS * 2)    // 30720

__global__ __launch_bounds__(256, 2)
void mma_gemm(const __nv_bfloat16* __restrict__ Ah, const __nv_bfloat16* __restrict__ Al,
              const __nv_bfloat16* __restrict__ Bh, const __nv_bfloat16* __restrict__ Bl,
              const float* __restrict__ bias,
              __nv_bfloat16* __restrict__ qh, __nv_bfloat16* __restrict__ ql,
              __nv_bfloat16* __restrict__ kh, __nv_bfloat16* __restrict__ kl,
              __nv_bfloat16* __restrict__ vh, __nv_bfloat16* __restrict__ vl,
              float* __restrict__ oplain, int mode)
{
    extern __shared__ char sm[];
    const uint32_t sbase = smem_u32(sm);
    const int tid = threadIdx.x;
    const int wid = tid >> 5, lane = tid & 31;
    const int wm = wid & 3, wn = wid >> 2;       // 4 M-warps x 2 N-warps
    const int n0 = blockIdx.x * 64;
    const int m0 = blockIdx.y * 128;

    const int a_row = lane & 15;
    const int a_col = (lane >> 4) << 3;
    const int b_row = ((lane >> 4) << 3) + (lane & 7);
    const int b_col = ((lane >> 3) & 1) << 3;

    float c[2][4][4] = {};    // [mi][nt][reg] : warp tile 32x32

    auto stage_load = [&](int buf, int k0) {
        #pragma unroll
        for (int t = 0; t < 6; ++t) {
            const int idx = t * 256 + tid;       // 0..1535
            if (idx < 1024) {                    // A arrays (compile-time per t)
                const int arr = idx >> 9;        // 0:Ah 1:Al
                const int local = idx & 511;
                const int r = local >> 2, seg = local & 3;
                const __nv_bfloat16* g = (arr ? Al : Ah)
                    + (size_t)(m0 + r) * EE + k0 + seg * 8;
                uint32_t dst = sbase + buf * STAGE_BYTES
                    + (uint32_t)(arr * A_ELEMS + r * PITCH + seg * 8) * 2;
                CP_ASYNC16(dst, g);
            } else {                             // B arrays
                const int j = idx - 1024;
                const int arr = j >> 8;          // 0:Bh 1:Bl
                const int local = j & 255;
                const int r = local >> 2, seg = local & 3;
                const __nv_bfloat16* g = (arr ? Bl : Bh)
                    + (size_t)(n0 + r) * EE + k0 + seg * 8;
                uint32_t dst = sbase + buf * STAGE_BYTES
                    + (uint32_t)(2 * A_ELEMS + arr * B_ELEMS + r * PITCH + seg * 8) * 2;
                CP_ASYNC16(dst, g);
            }
        }
        CP_COMMIT();
    };

    stage_load(0, 0);
    stage_load(1, 32);

    for (int ch = 0; ch < 32; ++ch) {
        if (ch < 31) asm volatile("cp.async.wait_group 1;" ::: "memory");
        else         asm volatile("cp.async.wait_group 0;" ::: "memory");
        __syncthreads();

        const uint32_t sAh = sbase + (ch & 1) * STAGE_BYTES;
        const uint32_t sAl = sAh + A_ELEMS * 2;
        const uint32_t sBh = sAh + 2 * A_ELEMS * 2;
        const uint32_t sBl = sBh + B_ELEMS * 2;

        #pragma unroll
        for (int ks = 0; ks < 2; ++ks) {
            uint32_t ah[2][4], alr[2][4], bh[2][4], bl[2][4];
            #pragma unroll
            for (int mi = 0; mi < 2; ++mi) {
                uint32_t off = (uint32_t)((wm * 32 + mi * 16 + a_row) * PITCH
                                          + ks * 16 + a_col) * 2;
                LDSM4(ah[mi],  sAh + off);
                LDSM4(alr[mi], sAl + off);
            }
            #pragma unroll
            for (int jp = 0; jp < 2; ++jp) {
                uint32_t off = (uint32_t)((wn * 32 + jp * 16 + b_row) * PITCH
                                          + ks * 16 + b_col) * 2;
                LDSM4(bh[jp], sBh + off);
                LDSM4(bl[jp], sBl + off);
            }
            #pragma unroll
            for (int p = 0; p < 3; ++p)
                #pragma unroll
                for (int mi = 0; mi < 2; ++mi)
                    #pragma unroll
                    for (int nt = 0; nt < 4; ++nt) {
                        const int jp = nt >> 1, q = (nt & 1) * 2;
                        if (p == 0)
                            MMA16816(c[mi][nt], ah[mi],  bh[jp][q], bh[jp][q + 1]);
                        else if (p == 1)
                            MMA16816(c[mi][nt], ah[mi],  bl[jp][q], bl[jp][q + 1]);
                        else
                            MMA16816(c[mi][nt], alr[mi], bh[jp][q], bh[jp][q + 1]);
                    }
        }
        __syncthreads();
        if (ch + 2 < 32) stage_load(ch & 1, (ch + 2) * 32);
    }

    const int rbase = m0 + wm * 32 + (lane >> 2);
    const int cpair = (lane & 3) * 2;

    if (mode == 0) {
        const int which = n0 >> 10;              // 64-wide tile = exactly one head
        __nv_bfloat16 *dh, *dl;
        if (which == 0)      { dh = qh; dl = ql; }
        else if (which == 1) { dh = kh; dl = kl; }
        else                 { dh = vh; dl = vl; }
        const float sc = (which == 0) ? SCALE_Q : 1.0f;
        const int h = (n0 & 1023) >> 6;
        #pragma unroll
        for (int mi = 0; mi < 2; ++mi) {
            const int m1 = rbase + mi * 16;
            const int m2 = m1 + 8;
            const size_t base1 = (((size_t)(m1 >> 11) * HH + h) * TT + (m1 & 2047)) * DD;
            const size_t base2 = (((size_t)(m2 >> 11) * HH + h) * TT + (m2 & 2047)) * DD;
            #pragma unroll
            for (int nt = 0; nt < 4; ++nt) {
                const int d = wn * 32 + nt * 8 + cpair;
                uint32_t h1, l1, h2, l2;
                split2(c[mi][nt][0] * sc, c[mi][nt][1] * sc, h1, l1);
                split2(c[mi][nt][2] * sc, c[mi][nt][3] * sc, h2, l2);
                *(uint32_t*)(dh + base1 + d) = h1;
                *(uint32_t*)(dl + base1 + d) = l1;
                *(uint32_t*)(dh + base2 + d) = h2;
                *(uint32_t*)(dl + base2 + d) = l2;
            }
        }
    } else {
        #pragma unroll
        for (int mi = 0; mi < 2; ++mi) {
            const int m1 = rbase + mi * 16;
            float* r1 = oplain + (size_t)m1 * EE;
            float* r2 = oplain + (size_t)(m1 + 8) * EE;
            #pragma unroll
            for (int nt = 0; nt < 4; ++nt) {
                const int col = n0 + wn * 32 + nt * 8 + cpair;
                const float b0 = bias[col], b1v = bias[col + 1];
                float2 v1 = make_float2(c[mi][nt][0] + b0, c[mi][nt][1] + b1v);
                float2 v2 = make_float2(c[mi][nt][2] + b0, c[mi][nt][3] + b1v);
                *(float2*)(r1 + col) = v1;
                *(float2*)(r2 + col) = v2;
            }
        }
    }
}

// ---------------------------------------------------------------------------
// Tensor-core causal flash attention (unchanged from R5).
// ---------------------------------------------------------------------------
#define AP 72
#define SM_Q 0
#define QARR (128 * AP * 2)
#define SM_STAGE (2 * QARR)
#define KVARR (64 * AP * 2)
#define STAGE_SZ (4 * KVARR)
#define SM_MASK (SM_STAGE + 2 * STAGE_SZ)
#define SM_TOTAL (SM_MASK + 512)

__global__ __launch_bounds__(256, 1)
void attn_mma(const __nv_bfloat16* __restrict__ qh, const __nv_bfloat16* __restrict__ ql,
              const __nv_bfloat16* __restrict__ kh, const __nv_bfloat16* __restrict__ kl,
              const __nv_bfloat16* __restrict__ vh, const __nv_bfloat16* __restrict__ vl,
              const float* __restrict__ amask, float* __restrict__ ctx)
{
    extern __shared__ char sm[];
    const uint32_t sbase = smem_u32(sm);
    const int tid = threadIdx.x;
    const int w = tid >> 5, lane = tid & 31;
    const int bh = blockIdx.x;
    const int b_ = bh >> 4, h = bh & 15;
    const int qt = 15 - blockIdx.y;
    const int q0 = qt * 128;
    const int last = 2 * qt + 1;

    const int a_row = lane & 15;
    const int a_col = (lane >> 4) << 3;
    const int b_row = ((lane >> 4) << 3) + (lane & 7);
    const int b_col = ((lane >> 3) & 1) << 3;
    const int v_key = (lane & 7) + (((lane >> 3) & 1) << 3);
    const int v_d   = (lane >> 4) << 3;

    const size_t gbase = (size_t)bh * TT * DD;

    auto load_q = [&]() {
        #pragma unroll
        for (int arr = 0; arr < 2; ++arr) {
            const __nv_bfloat16* src0 = arr ? ql : qh;
            #pragma unroll
            for (int half = 0; half < 4; ++half) {
                int loc = half * 256 + tid;
                int r = loc >> 3, seg = loc & 7;
                const __nv_bfloat16* src = src0 + gbase + (size_t)(q0 + r) * DD + seg * 8;
                uint32_t dst = sbase + SM_Q + arr * QARR + (uint32_t)(r * AP + seg * 8) * 2;
                CP_ASYNC16(dst, src);
            }
        }
    };
    auto load_kv = [&](int buf, int kt) {
        const int s0 = kt * 64;
        #pragma unroll
        for (int arr = 0; arr < 4; ++arr) {
            const __nv_bfloat16* src0 = (arr == 0) ? kh : (arr == 1) ? kl
                                       : (arr == 2) ? vh : vl;
            #pragma unroll
            for (int half = 0; half < 2; ++half) {
                int loc = half * 256 + tid;
                int r = loc >> 3, seg = loc & 7;
                const __nv_bfloat16* src = src0 + gbase + (size_t)(s0 + r) * DD + seg * 8;
                uint32_t dst = sbase + SM_STAGE + buf * STAGE_SZ + arr * KVARR
                             + (uint32_t)(r * AP + seg * 8) * 2;
                CP_ASYNC16(dst, src);
            }
        }
        if (tid < 16) {
            const float* msrc = amask + (size_t)b_ * TT + s0 + tid * 4;
            uint32_t mdst = sbase + SM_MASK + buf * 256 + tid * 16;
            CP_ASYNC16(mdst, msrc);
        }
    };

    load_q();
    load_kv(0, 0);
    CP_COMMIT();
    load_kv(1, 1);
    CP_COMMIT();
    asm volatile("cp.async.wait_group 1;" ::: "memory");
    __syncthreads();

    uint32_t qa_h[4][4], qa_l[4][4];
    #pragma unroll
    for (int ks = 0; ks < 4; ++ks) {
        uint32_t off = (uint32_t)((w * 16 + a_row) * AP + ks * 16 + a_col) * 2;
        LDSM4(qa_h[ks], sbase + SM_Q + off);
        LDSM4(qa_l[ks], sbase + SM_Q + QARR + off);
    }

    float o[8][4] = {};
    float m0r = -1e30f, m1r = -1e30f, l0 = 0.f, l1 = 0.f;
    const int row0 = q0 + w * 16 + (lane >> 2);
    const int wrow_hi = q0 + w * 16 + 15;

    for (int kt = 0; kt <= last; ++kt) {
        const int buf = kt & 1;
        const int s0 = kt * 64;
        const bool active = (s0 <= wrow_hi);

        if (active) {
            const uint32_t kb = sbase + SM_STAGE + buf * STAGE_SZ;
            float c[8][4] = {};
            #pragma unroll
            for (int ks = 0; ks < 4; ++ks) {
                uint32_t kbh[4][4], kbl[4][4];
                #pragma unroll
                for (int jp = 0; jp < 4; ++jp) {
                    uint32_t off = (uint32_t)((jp * 16 + b_row) * AP + ks * 16 + b_col) * 2;
                    LDSM4(kbh[jp], kb + off);
                    LDSM4(kbl[jp], kb + KVARR + off);
                }
                #pragma unroll
                for (int p = 0; p < 3; ++p)
                    #pragma unroll
                    for (int nt = 0; nt < 8; ++nt) {
                        const int jp = nt >> 1, q = (nt & 1) * 2;
                        if (p == 0)
                            MMA16816(c[nt], qa_h[ks], kbh[jp][q], kbh[jp][q + 1]);
                        else if (p == 1)
                            MMA16816(c[nt], qa_h[ks], kbl[jp][q], kbl[jp][q + 1]);
                        else
                            MMA16816(c[nt], qa_l[ks], kbh[jp][q], kbh[jp][q + 1]);
                    }
            }
            const float* mk = (const float*)(sm + SM_MASK + buf * 256);
            const bool dg = (s0 + 63) > (q0 + w * 16);
            #pragma unroll
            for (int nt = 0; nt < 8; ++nt) {
                const int cl = nt * 8 + (lane & 3) * 2;
                const float mv0 = mk[cl], mv1 = mk[cl + 1];
                const float ma0 = (1.0f - mv0) * -1e30f;
                const float ma1 = (1.0f - mv1) * -1e30f;
                c[nt][0] += ma0; c[nt][1] += ma1;
                c[nt][2] += ma0; c[nt][3] += ma1;
                if (dg) {
                    const int cg = s0 + cl;
                    if (cg     > row0)     c[nt][0] = -1e30f;
                    if (cg + 1 > row0)     c[nt][1] = -1e30f;
                    if (cg     > row0 + 8) c[nt][2] = -1e30f;
                    if (cg + 1 > row0 + 8) c[nt][3] = -1e30f;
                }
            }
            float t0 = -1e30f, t1 = -1e30f;
            #pragma unroll
            for (int nt = 0; nt < 8; ++nt) {
                t0 = fmaxf(t0, fmaxf(c[nt][0], c[nt][1]));
                t1 = fmaxf(t1, fmaxf(c[nt][2], c[nt][3]));
            }
            t0 = fmaxf(t0, __shfl_xor_sync(0xffffffffu, t0, 1));
            t0 = fmaxf(t0, __shfl_xor_sync(0xffffffffu, t0, 2));
            t1 = fmaxf(t1, __shfl_xor_sync(0xffffffffu, t1, 1));
            t1 = fmaxf(t1, __shfl_xor_sync(0xffffffffu, t1, 2));
            const float mn0 = fmaxf(m0r, t0), mn1 = fmaxf(m1r, t1);
            const float cor0 = exp2fast(m0r - mn0), cor1 = exp2fast(m1r - mn1);
            m0r = mn0; m1r = mn1;
            l0 *= cor0; l1 *= cor1;
            #pragma unroll
            for (int nt = 0; nt < 8; ++nt) {
                o[nt][0] *= cor0; o[nt][1] *= cor0;
                o[nt][2] *= cor1; o[nt][3] *= cor1;
            }
            uint32_t pah[4][4], pal[4][4];
            float s0sum = 0.f, s1sum = 0.f;
            #pragma unroll
            for (int nt = 0; nt < 8; ++nt) {
                const float p0 = exp2fast(c[nt][0] - mn0);
                const float p1 = exp2fast(c[nt][1] - mn0);
                const float p2 = exp2fast(c[nt][2] - mn1);
                const float p3 = exp2fast(c[nt][3] - mn1);
                s0sum += p0 + p1; s1sum += p2 + p3;
                const int ks = nt >> 1;
                const int base = (nt & 1) * 2;
                split2(p0, p1, pah[ks][base], pal[ks][base]);
                split2(p2, p3, pah[ks][base + 1], pal[ks][base + 1]);
            }
            s0sum += __shfl_xor_sync(0xffffffffu, s0sum, 1);
            s0sum += __shfl_xor_sync(0xffffffffu, s0sum, 2);
            s1sum += __shfl_xor_sync(0xffffffffu, s1sum, 1);
            s1sum += __shfl_xor_sync(0xffffffffu, s1sum, 2);
            l0 += s0sum; l1 += s1sum;
            #pragma unroll
            for (int ks = 0; ks < 4; ++ks) {
                uint32_t vbh[4][4], vbl[4][4];
                #pragma unroll
                for (int jp = 0; jp < 4; ++jp) {
                    uint32_t off = (uint32_t)((ks * 16 + v_key) * AP + jp * 16 + v_d) * 2;
                    LDSM4T(vbh[jp], kb + 2 * KVARR + off);
                    LDSM4T(vbl[jp], kb + 3 * KVARR + off);
                }
                #pragma unroll
                for (int p = 0; p < 3; ++p)
                    #pragma unroll
                    for (int nt = 0; nt < 8; ++nt) {
                        const int jp = nt >> 1, q = (nt & 1) * 2;
                        if (p == 0)
                            MMA16816(o[nt], pah[ks], vbh[jp][q], vbh[jp][q + 1]);
                        else if (p == 1)
                            MMA16816(o[nt], pah[ks], vbl[jp][q], vbl[jp][q + 1]);
                        else
                            MMA16816(o[nt], pal[ks], vbh[jp][q], vbh[jp][q + 1]);
                    }
            }
        }
        __syncthreads();
        if (kt + 2 <= last) { load_kv(buf, kt + 2); CP_COMMIT(); }
        if (kt < last) {
            if (kt + 2 <= last) asm volatile("cp.async.wait_group 1;" ::: "memory");
            else                asm volatile("cp.async.wait_group 0;" ::: "memory");
            __syncthreads();
        }
    }

    const float inv0 = 1.0f / l0, inv1 = 1.0f / l1;
    const int cpair = (lane & 3) * 2;
    float* r1 = ctx + ((size_t)b_ * TT + row0) * EE + h * 64;
    float* r2 = ctx + ((size_t)b_ * TT + row0 + 8) * EE + h * 64;
    #pragma unroll
    for (int nt = 0; nt < 8; ++nt) {
        const int d = nt * 8 + cpair;
        *(float2*)(r1 + d) = make_float2(o[nt][0] * inv0, o[nt][1] * inv0);
        *(float2*)(r2 + d) = make_float2(o[nt][2] * inv1, o[nt][3] * inv1);
    }
}

// ---------------------------------------------------------------------------
// Launch
// ---------------------------------------------------------------------------
extern "C" void kernel_launch(void* const* d_in, const int* in_sizes, int n_in,
                              void* d_out, int out_size)
{
    const float* x     = (const float*)d_in[0];
    const float* amask = (const float*)d_in[1];
    const float* Wq    = (const float*)d_in[2];
    const float* Wk    = (const float*)d_in[3];
    const float* Wv    = (const float*)d_in[4];
    const float* Wo    = (const float*)d_in[5];
    const float* bo    = (const float*)d_in[6];
    float* out = (float*)d_out;

    float* ctx;
    __nv_bfloat16 *xhi, *xlo, *wth, *wtl, *woh, *wol, *chi, *clo;
    __nv_bfloat16 *qh, *ql, *kh, *kl, *vh, *vl;
    cudaGetSymbolAddress((void**)&ctx, g_ctx);
    cudaGetSymbolAddress((void**)&xhi, g_xhi);
    cudaGetSymbolAddress((void**)&xlo, g_xlo);
    cudaGetSymbolAddress((void**)&wth, g_wth);
    cudaGetSymbolAddress((void**)&wtl, g_wtl);
    cudaGetSymbolAddress((void**)&woh, g_woh);
    cudaGetSymbolAddress((void**)&wol, g_wol);
    cudaGetSymbolAddress((void**)&chi, g_chi);
    cudaGetSymbolAddress((void**)&clo, g_clo);
    cudaGetSymbolAddress((void**)&qh,  g_qh);
    cudaGetSymbolAddress((void**)&ql,  g_ql);
    cudaGetSymbolAddress((void**)&kh,  g_kh);
    cudaGetSymbolAddress((void**)&kl,  g_kl);
    cudaGetSymbolAddress((void**)&vh,  g_vh);
    cudaGetSymbolAddress((void**)&vl,  g_vl);

    cudaFuncSetAttribute(mma_gemm, cudaFuncAttributeMaxDynamicSharedMemorySize,
                         2 * STAGE_BYTES);
    cudaFuncSetAttribute(attn_mma, cudaFuncAttributeMaxDynamicSharedMemorySize,
                         SM_TOTAL);

    conv_hilo<<<(BT * EE / 4) / 256, 256>>>(x, xhi, xlo, BT * EE / 4);
    prep_wt<<<768, 256>>>(Wq, Wk, Wv, wth, wtl);
    conv_hilo<<<(EE * EE / 4) / 256, 256>>>(Wo, woh, wol, EE * EE / 4);

    {   // QKV projection -> bf16 hi/lo q,k,v
        dim3 grid(NQKV / 64, BT / 128);
        mma_gemm<<<grid, 256, 2 * STAGE_BYTES>>>(xhi, xlo, wth, wtl, nullptr,
                                                 qh, ql, kh, kl, vh, vl,
                                                 nullptr, 0);
    }
    {   // attention
        dim3 grid(BB * HH, TT / 128);
        attn_mma<<<grid, 256, SM_TOTAL>>>(qh, ql, kh, kl, vh, vl, amask, ctx);
    }
    conv_hilo<<<(BT * EE / 4) / 256, 256>>>(ctx, chi, clo, BT * EE / 4);
    {   // output projection
        dim3 grid(EE / 64, BT / 128);
        mma_gemm<<<grid, 256, 2 * STAGE_BYTES>>>(chi, clo, woh, wol, bo,
                                                 nullptr, nullptr, nullptr,
                                                 nullptr, nullptr, nullptr,
                                                 out, 1);
    }
}